// round 7
// baseline (speedup 1.0000x reference)
#include <cuda_runtime.h>
#include <cuda_bf16.h>
#include <math.h>

// ---------------------------------------------------------------------------
// Problem constants
//   B=32, L=32768, PS=32, T=1024, D=256, 3D=768
// ---------------------------------------------------------------------------
#define BATCH 32
#define LSEQ  32768
#define PS    32
#define TPATCH 1024
#define DMODEL 256
#define ROWS_TOTAL (BATCH * TPATCH)   // 32768

// Scratch (static device memory; no allocations allowed)
__device__ float g_xnorm[BATCH * LSEQ];            // 4 MB
__device__ float g_h    [ROWS_TOTAL * DMODEL];     // 32 MB
__device__ float g_qkv  [ROWS_TOTAL * 3 * DMODEL]; // 96 MB
__device__ float g_attn [ROWS_TOTAL * DMODEL];     // 32 MB
__device__ float g_out2 [ROWS_TOTAL * DMODEL];     // 32 MB
__device__ float g_partials[4096];

// ---------------------------------------------------------------------------
// Kernel 1: instance norm over full series (per batch row), ddof=1
// ---------------------------------------------------------------------------
__global__ void __launch_bounds__(1024) norm_kernel(const float* __restrict__ x,
                                                    float* __restrict__ xn)
{
    __shared__ float s1[1024];
    __shared__ float s2[1024];
    const int b = blockIdx.x;
    const int tid = threadIdx.x;
    const float* xb = x + (size_t)b * LSEQ;
    float v[32];
    float sum = 0.f, sq = 0.f;
#pragma unroll
    for (int u = 0; u < 32; ++u) {
        v[u] = xb[tid + u * 1024];
        sum += v[u];
        sq  += v[u] * v[u];
    }
    s1[tid] = sum; s2[tid] = sq;
    __syncthreads();
    for (int st = 512; st > 0; st >>= 1) {
        if (tid < st) { s1[tid] += s1[tid + st]; s2[tid] += s2[tid + st]; }
        __syncthreads();
    }
    const float mean = s1[0] * (1.0f / (float)LSEQ);
    const float var  = (s2[0] - (float)LSEQ * mean * mean) * (1.0f / (float)(LSEQ - 1));
    const float inv  = 1.0f / (sqrtf(var) + 1e-5f);
    float* xo = xn + (size_t)b * LSEQ;
#pragma unroll
    for (int u = 0; u < 32; ++u)
        xo[tid + u * 1024] = (v[u] - mean) * inv;
}

// ---------------------------------------------------------------------------
// Kernel 2: generic tiled GEMM with bias.  C[M,N] = A[M,K] @ B[K,N] + bias
// BM=128, BN=128, BK=16, 256 threads, 8x8 register tile per thread.
// ---------------------------------------------------------------------------
__global__ void __launch_bounds__(256) gemm_bias_kernel(
    const float* __restrict__ A, const float* __restrict__ B,
    const float* __restrict__ bias, float* __restrict__ C,
    int M, int N, int K)
{
    __shared__ float As[16 * 132];   // transposed A tile [k][m], padded
    __shared__ float Bs[16 * 128];   // B tile [k][n]

    const int tid = threadIdx.x;
    const int ty = tid >> 4;         // 0..15
    const int tx = tid & 15;         // 0..15
    const int m0 = blockIdx.x * 128;
    const int n0 = blockIdx.y * 128;

    float acc[8][8];
#pragma unroll
    for (int i = 0; i < 8; ++i)
#pragma unroll
        for (int j = 0; j < 8; ++j) acc[i][j] = 0.f;

    for (int k0 = 0; k0 < K; k0 += 16) {
        // A tile: 128x16 -> transposed in smem
        float4 av[2];
#pragma unroll
        for (int it = 0; it < 2; ++it) {
            int f = tid + it * 256;
            int row = f >> 2;
            int kc  = (f & 3) * 4;
            av[it] = *(const float4*)(A + (size_t)(m0 + row) * K + k0 + kc);
        }
        float4 bv[2];
#pragma unroll
        for (int it = 0; it < 2; ++it) {
            int f4 = tid + it * 256;
            int row = f4 >> 5;
            int c4  = f4 & 31;
            bv[it] = *(const float4*)(B + (size_t)(k0 + row) * N + n0 + c4 * 4);
        }
#pragma unroll
        for (int it = 0; it < 2; ++it) {
            int f = tid + it * 256;
            int row = f >> 2;
            int kc  = (f & 3) * 4;
            As[(kc + 0) * 132 + row] = av[it].x;
            As[(kc + 1) * 132 + row] = av[it].y;
            As[(kc + 2) * 132 + row] = av[it].z;
            As[(kc + 3) * 132 + row] = av[it].w;
            int f4 = f;
            int brow = f4 >> 5;
            int c4  = f4 & 31;
            *(float4*)&Bs[brow * 128 + c4 * 4] = bv[it];
        }
        __syncthreads();
#pragma unroll
        for (int k = 0; k < 16; ++k) {
            float4 a0 = *(const float4*)&As[k * 132 + ty * 8];
            float4 a1 = *(const float4*)&As[k * 132 + ty * 8 + 4];
            float4 b0 = *(const float4*)&Bs[k * 128 + tx * 4];
            float4 b1 = *(const float4*)&Bs[k * 128 + 64 + tx * 4];
            float af[8] = {a0.x, a0.y, a0.z, a0.w, a1.x, a1.y, a1.z, a1.w};
            float bf[8] = {b0.x, b0.y, b0.z, b0.w, b1.x, b1.y, b1.z, b1.w};
#pragma unroll
            for (int i = 0; i < 8; ++i)
#pragma unroll
                for (int j = 0; j < 8; ++j)
                    acc[i][j] += af[i] * bf[j];
        }
        __syncthreads();
    }

    float4 bb0 = *(const float4*)&bias[n0 + tx * 4];
    float4 bb1 = *(const float4*)&bias[n0 + 64 + tx * 4];
#pragma unroll
    for (int i = 0; i < 8; ++i) {
        size_t row = (size_t)(m0 + ty * 8 + i);
        float4 c0 = make_float4(acc[i][0] + bb0.x, acc[i][1] + bb0.y,
                                acc[i][2] + bb0.z, acc[i][3] + bb0.w);
        float4 c1 = make_float4(acc[i][4] + bb1.x, acc[i][5] + bb1.y,
                                acc[i][6] + bb1.z, acc[i][7] + bb1.w);
        *(float4*)(C + row * N + n0 + tx * 4)      = c0;
        *(float4*)(C + row * N + n0 + 64 + tx * 4) = c1;
    }
}

// ---------------------------------------------------------------------------
// Kernel 3: causal flash attention, fp32.
// One block = (batch b, q-tile of 64 rows).  K/V tiles of 64 keys.
// qkv row layout: [q(256) | k(256) | v(256)].
// iq = tid>>4 owns rows {iq+16r}; same rows in S and PV phase so m/l stay
// in registers.  smem rows strided 260 floats (float4-aligned).
// ---------------------------------------------------------------------------
#define ATTN_SMEM_BYTES ((64 * 260 * 3 + 64 * 65) * 4)

__global__ void __launch_bounds__(256, 1) attn_kernel(
    const float* __restrict__ qkv, float* __restrict__ outp)
{
    extern __shared__ float smbuf[];
    float* Qs = smbuf;                 // 64 x 260
    float* Ks = Qs + 64 * 260;
    float* Vs = Ks + 64 * 260;
    float* Ps = Vs + 64 * 260;         // 64 x 65

    const int b  = blockIdx.y;
    const int qt = (int)gridDim.x - 1 - (int)blockIdx.x;  // heavy tiles first
    const int q0 = qt * 64;
    const int tid = threadIdx.x;
    const int iq = tid >> 4;           // 0..15
    const int jq = tid & 15;           // 0..15

    // load Q tile (64 x 256)
    const float* qbase = qkv + (size_t)(b * TPATCH + q0) * 768;
#pragma unroll
    for (int it = 0; it < 16; ++it) {
        int f = tid + it * 256;        // float4 index 0..4095
        int r = f >> 6;
        int c4 = f & 63;
        float4 v = *(const float4*)(qbase + (size_t)r * 768 + c4 * 4);
        *(float4*)&Qs[r * 260 + c4 * 4] = v;
    }

    float m[4], l[4];
    float4 o[4][4];
#pragma unroll
    for (int r = 0; r < 4; ++r) {
        m[r] = -1e30f; l[r] = 0.f;
#pragma unroll
        for (int c = 0; c < 4; ++c) o[r][c] = make_float4(0.f, 0.f, 0.f, 0.f);
    }

    const float cexp = 0.0625f * 1.4426950408889634f;  // scale * log2(e)

    for (int kt = 0; kt <= qt; ++kt) {
        __syncthreads();   // covers Q-load (first iter) and prev-iter Vs/Ps reads
        const int k0 = kt * 64;
        const float* kb = qkv + (size_t)(b * TPATCH + k0) * 768 + 256;
        const float* vb = kb + 256;
#pragma unroll
        for (int it = 0; it < 16; ++it) {
            int f = tid + it * 256;
            int r = f >> 6;
            int c4 = f & 63;
            float4 kv = *(const float4*)(kb + (size_t)r * 768 + c4 * 4);
            float4 vv = *(const float4*)(vb + (size_t)r * 768 + c4 * 4);
            *(float4*)&Ks[r * 260 + c4 * 4] = kv;
            *(float4*)&Vs[r * 260 + c4 * 4] = vv;
        }
        __syncthreads();

        // ---- S = Q K^T  (4x4 per thread) ----
        float s[4][4];
#pragma unroll
        for (int r = 0; r < 4; ++r)
#pragma unroll
            for (int c = 0; c < 4; ++c) s[r][c] = 0.f;

#pragma unroll 4
        for (int d4 = 0; d4 < 64; ++d4) {
            float4 qf[4], kf[4];
#pragma unroll
            for (int r = 0; r < 4; ++r)
                qf[r] = *(const float4*)&Qs[(iq + 16 * r) * 260 + d4 * 4];
#pragma unroll
            for (int c = 0; c < 4; ++c)
                kf[c] = *(const float4*)&Ks[(jq + 16 * c) * 260 + d4 * 4];
#pragma unroll
            for (int r = 0; r < 4; ++r)
#pragma unroll
                for (int c = 0; c < 4; ++c)
                    s[r][c] += qf[r].x * kf[c].x + qf[r].y * kf[c].y +
                               qf[r].z * kf[c].z + qf[r].w * kf[c].w;
        }

        // ---- causal mask on diagonal tile ----
        if (kt == qt) {
#pragma unroll
            for (int r = 0; r < 4; ++r)
#pragma unroll
                for (int c = 0; c < 4; ++c)
                    if (jq + 16 * c > iq + 16 * r) s[r][c] = -1e30f;
        }

        // ---- online softmax (16 threads with same iq share the row set) ----
#pragma unroll
        for (int r = 0; r < 4; ++r) {
            float mx = fmaxf(fmaxf(s[r][0], s[r][1]), fmaxf(s[r][2], s[r][3]));
            mx = fmaxf(mx, __shfl_xor_sync(0xffffffffu, mx, 1));
            mx = fmaxf(mx, __shfl_xor_sync(0xffffffffu, mx, 2));
            mx = fmaxf(mx, __shfl_xor_sync(0xffffffffu, mx, 4));
            mx = fmaxf(mx, __shfl_xor_sync(0xffffffffu, mx, 8));
            float mnew = fmaxf(m[r], mx);
            float fac = exp2f((m[r] - mnew) * cexp);
            m[r] = mnew;
            float ls = 0.f;
#pragma unroll
            for (int c = 0; c < 4; ++c) {
                float p = exp2f((s[r][c] - mnew) * cexp);
                s[r][c] = p;
                ls += p;
            }
            ls += __shfl_xor_sync(0xffffffffu, ls, 1);
            ls += __shfl_xor_sync(0xffffffffu, ls, 2);
            ls += __shfl_xor_sync(0xffffffffu, ls, 4);
            ls += __shfl_xor_sync(0xffffffffu, ls, 8);
            l[r] = l[r] * fac + ls;
#pragma unroll
            for (int c = 0; c < 4; ++c) {
                o[r][c].x *= fac; o[r][c].y *= fac;
                o[r][c].z *= fac; o[r][c].w *= fac;
            }
#pragma unroll
            for (int c = 0; c < 4; ++c)
                Ps[(iq + 16 * r) * 65 + jq + 16 * c] = s[r][c];
        }
        __syncthreads();

        // ---- O += P V  (4 rows x 16 cols per thread) ----
#pragma unroll 2
        for (int j = 0; j < 64; ++j) {
            float pr[4];
#pragma unroll
            for (int r = 0; r < 4; ++r) pr[r] = Ps[(iq + 16 * r) * 65 + j];
#pragma unroll
            for (int c = 0; c < 4; ++c) {
                float4 v = *(const float4*)&Vs[j * 260 + jq * 4 + 64 * c];
#pragma unroll
                for (int r = 0; r < 4; ++r) {
                    o[r][c].x += pr[r] * v.x;
                    o[r][c].y += pr[r] * v.y;
                    o[r][c].z += pr[r] * v.z;
                    o[r][c].w += pr[r] * v.w;
                }
            }
        }
    }

    // ---- finalize: O / l, write out ----
#pragma unroll
    for (int r = 0; r < 4; ++r) {
        float inv = 1.0f / l[r];
        float* op = outp + (size_t)(b * TPATCH + q0 + iq + 16 * r) * DMODEL;
#pragma unroll
        for (int c = 0; c < 4; ++c) {
            float4 v = o[r][c];
            v.x *= inv; v.y *= inv; v.z *= inv; v.w *= inv;
            *(float4*)(op + jq * 4 + 64 * c) = v;
        }
    }
}

// ---------------------------------------------------------------------------
// Kernel 4: head GEMM (256->32) fused with next-patch MSE partial sums.
// ---------------------------------------------------------------------------
__global__ void __launch_bounds__(256) head_loss_kernel(
    const float* __restrict__ X,    // [32768, 256]
    const float* __restrict__ Wh,   // [256, 32]
    const float* __restrict__ bh,   // [32]
    const float* __restrict__ xn,   // [32, 32768]
    float* __restrict__ partials)
{
    __shared__ float Ws[256 * 32];
    __shared__ float wsum[8];
    const int tid = threadIdx.x;
    const int lane = tid & 31;
    const int w = tid >> 5;

    for (int idx = tid; idx < 256 * 32; idx += 256) Ws[idx] = Wh[idx];
    __syncthreads();

    const int row = blockIdx.x * 8 + w;
    const float* xr = X + (size_t)row * 256;
    float r[8];
#pragma unroll
    for (int k8 = 0; k8 < 8; ++k8) r[k8] = xr[k8 * 32 + lane];

    float acc = 0.f;
#pragma unroll
    for (int k8 = 0; k8 < 8; ++k8) {
#pragma unroll
        for (int ll = 0; ll < 32; ++ll) {
            float v = __shfl_sync(0xffffffffu, r[k8], ll);
            acc += v * Ws[(k8 * 32 + ll) * 32 + lane];
        }
    }

    const int bidx = row >> 10;
    const int t = row & 1023;
    float sq = 0.f;
    if (t < TPATCH - 1) {
        float pred = acc + bh[lane];
        float tgt = xn[(size_t)bidx * LSEQ + (t + 1) * 32 + lane];
        float d = pred - tgt;
        sq = d * d;
    }
#pragma unroll
    for (int off = 16; off > 0; off >>= 1)
        sq += __shfl_xor_sync(0xffffffffu, sq, off);
    if (lane == 0) wsum[w] = sq;
    __syncthreads();
    if (tid == 0) {
        float s = 0.f;
#pragma unroll
        for (int u = 0; u < 8; ++u) s += wsum[u];
        partials[blockIdx.x] = s;
    }
}

// ---------------------------------------------------------------------------
// Kernel 5: final deterministic reduction -> loss scalar
// ---------------------------------------------------------------------------
__global__ void __launch_bounds__(1024) final_reduce_kernel(
    const float* __restrict__ partials, float* __restrict__ out)
{
    __shared__ float sm2[1024];
    const int tid = threadIdx.x;
    float s = 0.f;
    for (int idx = tid; idx < 4096; idx += 1024) s += partials[idx];
    sm2[tid] = s;
    __syncthreads();
    for (int st = 512; st > 0; st >>= 1) {
        if (tid < st) sm2[tid] += sm2[tid + st];
        __syncthreads();
    }
    if (tid == 0)
        out[0] = sm2[0] / (float)(BATCH * (TPATCH - 1) * PS);  // / 1047552
}

// ---------------------------------------------------------------------------
// Launch
// ---------------------------------------------------------------------------
extern "C" void kernel_launch(void* const* d_in, const int* in_sizes, int n_in,
                              void* d_out, int out_size)
{
    const float* x      = (const float*)d_in[0];
    const float* W_proj = (const float*)d_in[1];
    const float* b_proj = (const float*)d_in[2];
    const float* W_qkv  = (const float*)d_in[3];
    const float* b_qkv  = (const float*)d_in[4];
    const float* W_out  = (const float*)d_in[5];
    const float* b_out  = (const float*)d_in[6];
    const float* W_head = (const float*)d_in[7];
    const float* b_head = (const float*)d_in[8];
    float* out = (float*)d_out;

    float *xn, *h, *qkv, *attn, *o2, *parts;
    cudaGetSymbolAddress((void**)&xn,    g_xnorm);
    cudaGetSymbolAddress((void**)&h,     g_h);
    cudaGetSymbolAddress((void**)&qkv,   g_qkv);
    cudaGetSymbolAddress((void**)&attn,  g_attn);
    cudaGetSymbolAddress((void**)&o2,    g_out2);
    cudaGetSymbolAddress((void**)&parts, g_partials);

    cudaFuncSetAttribute(attn_kernel,
                         cudaFuncAttributeMaxDynamicSharedMemorySize,
                         ATTN_SMEM_BYTES);

    // 1. instance norm
    norm_kernel<<<BATCH, 1024>>>(x, xn);
    // 2. patch embedding: [32768,32] @ [32,256] + b
    gemm_bias_kernel<<<dim3(ROWS_TOTAL / 128, DMODEL / 128), 256>>>(
        xn, W_proj, b_proj, h, ROWS_TOTAL, DMODEL, PS);
    // 3. qkv: [32768,256] @ [256,768] + b
    gemm_bias_kernel<<<dim3(ROWS_TOTAL / 128, (3 * DMODEL) / 128), 256>>>(
        h, W_qkv, b_qkv, qkv, ROWS_TOTAL, 3 * DMODEL, DMODEL);
    // 4. causal attention
    attn_kernel<<<dim3(TPATCH / 64, BATCH), 256, ATTN_SMEM_BYTES>>>(qkv, attn);
    // 5. output projection
    gemm_bias_kernel<<<dim3(ROWS_TOTAL / 128, DMODEL / 128), 256>>>(
        attn, W_out, b_out, o2, ROWS_TOTAL, DMODEL, DMODEL);
    // 6. head + loss partials
    head_loss_kernel<<<ROWS_TOTAL / 8, 256>>>(o2, W_head, b_head, xn, parts);
    // 7. final scalar
    final_reduce_kernel<<<1, 1024>>>(parts, out);
}

// round 11
// speedup vs baseline: 3.7624x; 3.7624x over previous
#include <cuda_runtime.h>
#include <cuda_bf16.h>
#include <math.h>
#include <stdint.h>

// ---------------------------------------------------------------------------
// Problem constants: B=32, L=32768, PS=32, T=1024, D=256
// ---------------------------------------------------------------------------
#define BATCH 32
#define LSEQ  32768
#define PS    32
#define TPATCH 1024
#define DMODEL 256
#define ROWS_TOTAL 32768

// smem row stride for bf16 tiles (264 b16 = 528 B; 132 words ≡ 4 mod 32 ->
// 8 consecutive ldmatrix rows land on disjoint bank groups)
#define ST 264

// ---------------------------------------------------------------------------
// Static device scratch
// ---------------------------------------------------------------------------
__device__ float         g_xnorm[BATCH * LSEQ];           // 4 MB fp32
__device__ __nv_bfloat16 g_hbf [ROWS_TOTAL * DMODEL];     // 16 MB
__device__ __nv_bfloat16 g_qbf [ROWS_TOTAL * DMODEL];
__device__ __nv_bfloat16 g_kbf [ROWS_TOTAL * DMODEL];
__device__ __nv_bfloat16 g_vbf [ROWS_TOTAL * DMODEL];
__device__ __nv_bfloat16 g_abf [ROWS_TOTAL * DMODEL];     // attn out
__device__ __nv_bfloat16 g_wqkvT[768 * 256];              // W_qkv^T bf16 [n][k]
__device__ __nv_bfloat16 g_woutT[256 * 256];              // W_out^T bf16 [n][k]
__device__ float         g_out2[ROWS_TOTAL * DMODEL];     // 32 MB fp32
__device__ float         g_partials[4096];

// ---------------------------------------------------------------------------
// Base-ISA tensor helpers: mma.sync m16n8k16 bf16 + ldmatrix (sm_80+ PTX)
// ---------------------------------------------------------------------------
__device__ __forceinline__ uint32_t smem_u32(const void* p) {
    uint32_t a;
    asm("{ .reg .u64 t; cvta.to.shared.u64 t, %1; cvt.u32.u64 %0, t; }"
        : "=r"(a) : "l"(p));
    return a;
}

__device__ __forceinline__ void mma_bf16(float d[4], const uint32_t a[4],
                                         const uint32_t b[2]) {
    asm volatile(
        "mma.sync.aligned.m16n8k16.row.col.f32.bf16.bf16.f32 "
        "{%0,%1,%2,%3}, {%4,%5,%6,%7}, {%8,%9}, {%0,%1,%2,%3};"
        : "+f"(d[0]), "+f"(d[1]), "+f"(d[2]), "+f"(d[3])
        : "r"(a[0]), "r"(a[1]), "r"(a[2]), "r"(a[3]), "r"(b[0]), "r"(b[1]));
}

__device__ __forceinline__ void ldmx4(uint32_t r[4], uint32_t addr) {
    asm volatile("ldmatrix.sync.aligned.m8n8.x4.shared.b16 {%0,%1,%2,%3}, [%4];"
        : "=r"(r[0]), "=r"(r[1]), "=r"(r[2]), "=r"(r[3]) : "r"(addr));
}
__device__ __forceinline__ void ldmx4t(uint32_t r[4], uint32_t addr) {
    asm volatile("ldmatrix.sync.aligned.m8n8.x4.trans.shared.b16 {%0,%1,%2,%3}, [%4];"
        : "=r"(r[0]), "=r"(r[1]), "=r"(r[2]), "=r"(r[3]) : "r"(addr));
}

__device__ __forceinline__ uint32_t pack_bf16x2(float a, float b) {
    __nv_bfloat162 h = __floats2bfloat162_rn(a, b);
    return *reinterpret_cast<uint32_t*>(&h);
}

// ---------------------------------------------------------------------------
// Kernel 1: instance norm (ddof=1), fp32 exact
// ---------------------------------------------------------------------------
__global__ void __launch_bounds__(1024) norm_kernel(const float* __restrict__ x,
                                                    float* __restrict__ xn)
{
    __shared__ float s1[1024];
    __shared__ float s2[1024];
    const int b = blockIdx.x, tid = threadIdx.x;
    const float* xb = x + (size_t)b * LSEQ;
    float v[32];
    float sum = 0.f, sq = 0.f;
#pragma unroll
    for (int u = 0; u < 32; ++u) {
        v[u] = xb[tid + u * 1024];
        sum += v[u]; sq += v[u] * v[u];
    }
    s1[tid] = sum; s2[tid] = sq;
    __syncthreads();
    for (int st = 512; st > 0; st >>= 1) {
        if (tid < st) { s1[tid] += s1[tid + st]; s2[tid] += s2[tid + st]; }
        __syncthreads();
    }
    const float mean = s1[0] * (1.0f / (float)LSEQ);
    const float var  = (s2[0] - (float)LSEQ * mean * mean) * (1.0f / (float)(LSEQ - 1));
    const float inv  = 1.0f / (sqrtf(var) + 1e-5f);
    float* xo = xn + (size_t)b * LSEQ;
#pragma unroll
    for (int u = 0; u < 32; ++u)
        xo[tid + u * 1024] = (v[u] - mean) * inv;
}

// ---------------------------------------------------------------------------
// Kernel 2: transpose+convert weights to bf16 [N,K]
// ---------------------------------------------------------------------------
__global__ void __launch_bounds__(256) conv_w_kernel(
    const float* __restrict__ Wq, const float* __restrict__ Wo,
    __nv_bfloat16* __restrict__ WqT, __nv_bfloat16* __restrict__ WoT)
{
    int i = blockIdx.x * 256 + threadIdx.x;
    if (i < 768 * 256) {
        int n = i >> 8, k = i & 255;
        WqT[i] = __float2bfloat16(Wq[k * 768 + n]);
    }
    if (i < 256 * 256) {
        int n = i >> 8, k = i & 255;
        WoT[i] = __float2bfloat16(Wo[k * 256 + n]);
    }
}

// ---------------------------------------------------------------------------
// Kernel 3: patch embedding (exact fp32 compute, bf16 output)
// ---------------------------------------------------------------------------
__global__ void __launch_bounds__(256) embed_kernel(
    const float* __restrict__ xn, const float* __restrict__ Wp,
    const float* __restrict__ bp, __nv_bfloat16* __restrict__ hbf)
{
    __shared__ float ps[128 * 32];
    const int tid = threadIdx.x;
    const int m0 = blockIdx.x * 128;
    const float* src = xn + (size_t)m0 * 32;
#pragma unroll
    for (int it = 0; it < 4; ++it)
        *(float4*)&ps[(tid + it * 256) * 4] = *(const float4*)(src + (tid + it * 256) * 4);
    __syncthreads();

    float w[32];
#pragma unroll
    for (int k = 0; k < 32; ++k) w[k] = Wp[k * 256 + tid];
    const float bias = bp[tid];

    for (int r = 0; r < 128; ++r) {
        float acc = bias;
#pragma unroll
        for (int k = 0; k < 32; ++k) acc += ps[r * 32 + k] * w[k];
        hbf[(size_t)(m0 + r) * 256 + tid] = __float2bfloat16(acc);
    }
}

// ---------------------------------------------------------------------------
// Kernel 4: mma.sync bf16 GEMM.  C[128,128] = A[m0.., :256] @ Wt[n0..,:256]^T
// 8 warps in 4(m) x 2(n): warp tile 32 x 64.  K=256 resident in smem.
// mode 1: route cols to q/k/v (bf16, row-major).  mode 0: fp32 out.
// ---------------------------------------------------------------------------
#define GEMM_DSMEM (2 * 128 * ST * 2)

__global__ void __launch_bounds__(256) gemm_mma_kernel(
    const __nv_bfloat16* __restrict__ A,
    const __nv_bfloat16* __restrict__ Wt,
    const float* __restrict__ bias,
    __nv_bfloat16* qout, __nv_bfloat16* kout, __nv_bfloat16* vout,
    float* fout, int mode)
{
    extern __shared__ __nv_bfloat16 sm[];
    __nv_bfloat16* As = sm;             // 128 x ST
    __nv_bfloat16* Bs = sm + 128 * ST;  // 128 x ST
    const uint32_t as_s = smem_u32(As), bs_s = smem_u32(Bs);

    const int tid = threadIdx.x, wid = tid >> 5, lane = tid & 31;
    const int m0 = blockIdx.x * 128, n0 = blockIdx.y * 128;
    const int wm = wid & 3, wn = wid >> 2;

    // fragment address offsets
    const int lr = lane & 7, lg = lane >> 3;
    const int a_ro = lr + (lg & 1) * 8, a_co = (lg >> 1) * 8;    // A frag
    const int b_ro = lr + (lg >> 1) * 8, b_co = (lg & 1) * 8;    // B frag

    // load tiles (128 rows x 256 cols bf16 each)
    const __nv_bfloat16* Ab = A + (size_t)m0 * 256;
    const __nv_bfloat16* Bb = Wt + (size_t)n0 * 256;
#pragma unroll
    for (int it = 0; it < 16; ++it) {
        int f = tid + it * 256;
        int row = f >> 5, c16 = f & 31;     // 32 x 16B chunks per row
        *(uint4*)(As + row * ST + c16 * 8) = *(const uint4*)(Ab + (size_t)row * 256 + c16 * 8);
        *(uint4*)(Bs + row * ST + c16 * 8) = *(const uint4*)(Bb + (size_t)row * 256 + c16 * 8);
    }
    __syncthreads();

    float O[2][8][4];
#pragma unroll
    for (int mi = 0; mi < 2; ++mi)
#pragma unroll
        for (int ni = 0; ni < 8; ++ni)
#pragma unroll
            for (int c = 0; c < 4; ++c) O[mi][ni][c] = 0.f;

    const uint32_t abase = as_s + ((wm * 32 + a_ro) * ST + a_co) * 2;
    const uint32_t bbase = bs_s + ((wn * 64 + b_ro) * ST + b_co) * 2;

#pragma unroll
    for (int kc = 0; kc < 16; ++kc) {
        uint32_t Af[2][4];
        ldmx4(Af[0], abase + kc * 32);
        ldmx4(Af[1], abase + 16 * ST * 2 + kc * 32);
#pragma unroll
        for (int t = 0; t < 4; ++t) {
            uint32_t Bf[4];
            ldmx4(Bf, bbase + t * 16 * ST * 2 + kc * 32);
            mma_bf16(O[0][2 * t],     Af[0], Bf);
            mma_bf16(O[0][2 * t + 1], Af[0], Bf + 2);
            mma_bf16(O[1][2 * t],     Af[1], Bf);
            mma_bf16(O[1][2 * t + 1], Af[1], Bf + 2);
        }
    }

    // epilogue
#pragma unroll
    for (int mi = 0; mi < 2; ++mi) {
        const int r0 = m0 + wm * 32 + mi * 16 + (lane >> 2);
        const int r1 = r0 + 8;
#pragma unroll
        for (int ni = 0; ni < 8; ++ni) {
            const int cg = n0 + wn * 64 + ni * 8 + (lane & 3) * 2;
            const float b0 = bias[cg], b1 = bias[cg + 1];
            if (mode == 0) {
                float2 v0 = make_float2(O[mi][ni][0] + b0, O[mi][ni][1] + b1);
                float2 v1 = make_float2(O[mi][ni][2] + b0, O[mi][ni][3] + b1);
                *(float2*)(fout + (size_t)r0 * 256 + cg) = v0;
                *(float2*)(fout + (size_t)r1 * 256 + cg) = v1;
            } else {
                __nv_bfloat16* base = (cg < 256) ? qout : (cg < 512) ? kout : vout;
                const int cc = cg & 255;
                *(uint32_t*)(base + (size_t)r0 * 256 + cc) =
                    pack_bf16x2(O[mi][ni][0] + b0, O[mi][ni][1] + b1);
                *(uint32_t*)(base + (size_t)r1 * 256 + cc) =
                    pack_bf16x2(O[mi][ni][2] + b0, O[mi][ni][3] + b1);
            }
        }
    }
}

// ---------------------------------------------------------------------------
// Kernel 5: causal flash attention via mma.sync.
// Block = (b, q-tile 128).  8 warps, warp owns 16 q-rows.
// S = Q K^T; softmax without max-subtraction (scores bounded, exp2 safe);
// P stays in registers (C-frag == A-frag layout); O += P V with V row-major
// via ldmatrix.trans.  O, l in registers across all K-tiles.
// ---------------------------------------------------------------------------
#define ATTN_DSMEM (3 * 128 * ST * 2)

__global__ void __launch_bounds__(256) attn_mma_kernel(
    const __nv_bfloat16* __restrict__ qg,
    const __nv_bfloat16* __restrict__ kg,
    const __nv_bfloat16* __restrict__ vg,
    __nv_bfloat16* __restrict__ og)
{
    extern __shared__ __nv_bfloat16 sm[];
    __nv_bfloat16* Qs = sm;
    __nv_bfloat16* Ks = sm + 128 * ST;
    __nv_bfloat16* Vs = sm + 2 * 128 * ST;
    const uint32_t qs_s = smem_u32(Qs), ks_s = smem_u32(Ks), vs_s = smem_u32(Vs);

    const int tid = threadIdx.x, wid = tid >> 5, lane = tid & 31;
    const int b = blockIdx.y;
    const int qt = 7 - (int)blockIdx.x;          // heavy tiles first
    const int q0 = qt * 128;
    const int m0 = wid * 16;                     // warp's q-row offset in tile

    const int lr = lane & 7, lg = lane >> 3;
    const int a_ro = lr + (lg & 1) * 8, a_co = (lg >> 1) * 8;   // A / trans-V
    const int b_ro = lr + (lg >> 1) * 8, b_co = (lg & 1) * 8;   // B (K)

    // load Q tile
    const __nv_bfloat16* qb = qg + (size_t)(b * TPATCH + q0) * 256;
#pragma unroll
    for (int it = 0; it < 16; ++it) {
        int f = tid + it * 256;
        int row = f >> 5, c16 = f & 31;
        *(uint4*)(Qs + row * ST + c16 * 8) = *(const uint4*)(qb + (size_t)row * 256 + c16 * 8);
    }
    __syncthreads();

    // cache Q fragments (16 k-chunks x 4 regs)
    uint32_t Qf[16][4];
    {
        const uint32_t qbase = qs_s + ((m0 + a_ro) * ST + a_co) * 2;
#pragma unroll
        for (int kc = 0; kc < 16; ++kc) ldmx4(Qf[kc], qbase + kc * 32);
    }

    float O[32][4];
#pragma unroll
    for (int i = 0; i < 32; ++i)
#pragma unroll
        for (int c = 0; c < 4; ++c) O[i][c] = 0.f;
    float l0 = 0.f, l1 = 0.f;

    const float cexp = 0.0625f * 1.4426950408889634f;   // 1/16 * log2(e)
    const int row0g = q0 + m0 + (lane >> 2);
    const int row1g = row0g + 8;

    for (int kt = 0; kt <= qt; ++kt) {
        __syncthreads();   // all warps done reading previous K/V
        const int k0 = kt * 128;
        const __nv_bfloat16* kb = kg + (size_t)(b * TPATCH + k0) * 256;
        const __nv_bfloat16* vb = vg + (size_t)(b * TPATCH + k0) * 256;
#pragma unroll
        for (int it = 0; it < 16; ++it) {
            int f = tid + it * 256;
            int row = f >> 5, c16 = f & 31;
            uint4 kv = *(const uint4*)(kb + (size_t)row * 256 + c16 * 8);
            uint4 vv = *(const uint4*)(vb + (size_t)row * 256 + c16 * 8);
            *(uint4*)(Ks + row * ST + c16 * 8) = kv;
            *(uint4*)(Vs + row * ST + c16 * 8) = vv;
        }
        __syncthreads();

        const bool diag = (kt == qt);
        const int nsteps = diag ? (wid + 1) : 8;   // skip fully-masked key blocks

        for (int j = 0; j < nsteps; ++j) {
            // ---- S = Q K^T for 16 keys ----
            float s0[4] = {0.f, 0.f, 0.f, 0.f};
            float s1[4] = {0.f, 0.f, 0.f, 0.f};
            const uint32_t bbase = ks_s + ((j * 16 + b_ro) * ST + b_co) * 2;
#pragma unroll
            for (int kc = 0; kc < 16; ++kc) {
                uint32_t Bf[4];
                ldmx4(Bf, bbase + kc * 32);
                mma_bf16(s0, Qf[kc], Bf);
                mma_bf16(s1, Qf[kc], Bf + 2);
            }

            // ---- softmax (no max subtraction) + causal mask ----
            const int c0g = k0 + j * 16 + (lane & 3) * 2;   // s0 keys; s1: +8
            float p0[4], p1[4];
#pragma unroll
            for (int c = 0; c < 4; ++c) {
                p0[c] = exp2f(s0[c] * cexp);
                p1[c] = exp2f(s1[c] * cexp);
            }
            if (diag) {
                if (c0g > row0g)         p0[0] = 0.f;
                if (c0g + 1 > row0g)     p0[1] = 0.f;
                if (c0g > row1g)         p0[2] = 0.f;
                if (c0g + 1 > row1g)     p0[3] = 0.f;
                if (c0g + 8 > row0g)     p1[0] = 0.f;
                if (c0g + 9 > row0g)     p1[1] = 0.f;
                if (c0g + 8 > row1g)     p1[2] = 0.f;
                if (c0g + 9 > row1g)     p1[3] = 0.f;
            }
            l0 += p0[0] + p0[1] + p1[0] + p1[1];
            l1 += p0[2] + p0[3] + p1[2] + p1[3];

            uint32_t P[4];
            P[0] = pack_bf16x2(p0[0], p0[1]);
            P[1] = pack_bf16x2(p0[2], p0[3]);
            P[2] = pack_bf16x2(p1[0], p1[1]);
            P[3] = pack_bf16x2(p1[2], p1[3]);

            // ---- O += P V (V row-major, trans ldmatrix) ----
            const uint32_t vbase = vs_s + ((j * 16 + a_ro) * ST + a_co) * 2;
#pragma unroll
            for (int dt = 0; dt < 16; ++dt) {
                uint32_t Vf[4];
                ldmx4t(Vf, vbase + dt * 32);
                mma_bf16(O[2 * dt],     P, Vf);
                mma_bf16(O[2 * dt + 1], P, Vf + 2);
            }
        }
    }

    // ---- finalize: row sums across quad, scale, write bf16 ----
    l0 += __shfl_xor_sync(0xffffffffu, l0, 1);
    l0 += __shfl_xor_sync(0xffffffffu, l0, 2);
    l1 += __shfl_xor_sync(0xffffffffu, l1, 1);
    l1 += __shfl_xor_sync(0xffffffffu, l1, 2);
    const float inv0 = 1.0f / l0, inv1 = 1.0f / l1;

    __nv_bfloat16* o0 = og + (size_t)(b * TPATCH + row0g) * 256;
    __nv_bfloat16* o1 = og + (size_t)(b * TPATCH + row1g) * 256;
#pragma unroll
    for (int i = 0; i < 32; ++i) {
        const int d0 = i * 8 + (lane & 3) * 2;
        *(uint32_t*)(o0 + d0) = pack_bf16x2(O[i][0] * inv0, O[i][1] * inv0);
        *(uint32_t*)(o1 + d0) = pack_bf16x2(O[i][2] * inv1, O[i][3] * inv1);
    }
}

// ---------------------------------------------------------------------------
// Kernel 6: head GEMM (256->32) fused with next-patch MSE partials (fp32)
// ---------------------------------------------------------------------------
__global__ void __launch_bounds__(256) head_loss_kernel(
    const float* __restrict__ X, const float* __restrict__ Wh,
    const float* __restrict__ bh, const float* __restrict__ xn,
    float* __restrict__ partials)
{
    __shared__ float Ws[256 * 32];
    __shared__ float wsum[8];
    const int tid = threadIdx.x, lane = tid & 31, w = tid >> 5;

    for (int idx = tid; idx < 256 * 32; idx += 256) Ws[idx] = Wh[idx];
    __syncthreads();

    const int row = blockIdx.x * 8 + w;
    const float* xr = X + (size_t)row * 256;
    float r[8];
#pragma unroll
    for (int k8 = 0; k8 < 8; ++k8) r[k8] = xr[k8 * 32 + lane];

    float acc = 0.f;
#pragma unroll
    for (int k8 = 0; k8 < 8; ++k8)
#pragma unroll
        for (int ll = 0; ll < 32; ++ll) {
            float v = __shfl_sync(0xffffffffu, r[k8], ll);
            acc += v * Ws[(k8 * 32 + ll) * 32 + lane];
        }

    const int bidx = row >> 10, t = row & 1023;
    float sq = 0.f;
    if (t < TPATCH - 1) {
        float pred = acc + bh[lane];
        float tgt = xn[(size_t)bidx * LSEQ + (t + 1) * 32 + lane];
        float d = pred - tgt;
        sq = d * d;
    }
#pragma unroll
    for (int off = 16; off > 0; off >>= 1)
        sq += __shfl_xor_sync(0xffffffffu, sq, off);
    if (lane == 0) wsum[w] = sq;
    __syncthreads();
    if (tid == 0) {
        float s = 0.f;
#pragma unroll
        for (int u = 0; u < 8; ++u) s += wsum[u];
        partials[blockIdx.x] = s;
    }
}

__global__ void __launch_bounds__(1024) final_reduce_kernel(
    const float* __restrict__ partials, float* __restrict__ out)
{
    __shared__ float sm2[1024];
    const int tid = threadIdx.x;
    float s = 0.f;
    for (int idx = tid; idx < 4096; idx += 1024) s += partials[idx];
    sm2[tid] = s;
    __syncthreads();
    for (int st = 512; st > 0; st >>= 1) {
        if (tid < st) sm2[tid] += sm2[tid + st];
        __syncthreads();
    }
    if (tid == 0)
        out[0] = sm2[0] / (float)(BATCH * (TPATCH - 1) * PS);
}

// ---------------------------------------------------------------------------
// Launch
// ---------------------------------------------------------------------------
extern "C" void kernel_launch(void* const* d_in, const int* in_sizes, int n_in,
                              void* d_out, int out_size)
{
    const float* x      = (const float*)d_in[0];
    const float* W_proj = (const float*)d_in[1];
    const float* b_proj = (const float*)d_in[2];
    const float* W_qkv  = (const float*)d_in[3];
    const float* b_qkv  = (const float*)d_in[4];
    const float* W_out  = (const float*)d_in[5];
    const float* b_out  = (const float*)d_in[6];
    const float* W_head = (const float*)d_in[7];
    const float* b_head = (const float*)d_in[8];
    float* out = (float*)d_out;

    float *xn, *o2, *parts;
    __nv_bfloat16 *hbf, *qbf, *kbf, *vbf, *abf, *wqT, *woT;
    cudaGetSymbolAddress((void**)&xn,   g_xnorm);
    cudaGetSymbolAddress((void**)&hbf,  g_hbf);
    cudaGetSymbolAddress((void**)&qbf,  g_qbf);
    cudaGetSymbolAddress((void**)&kbf,  g_kbf);
    cudaGetSymbolAddress((void**)&vbf,  g_vbf);
    cudaGetSymbolAddress((void**)&abf,  g_abf);
    cudaGetSymbolAddress((void**)&wqT,  g_wqkvT);
    cudaGetSymbolAddress((void**)&woT,  g_woutT);
    cudaGetSymbolAddress((void**)&o2,   g_out2);
    cudaGetSymbolAddress((void**)&parts, g_partials);

    cudaFuncSetAttribute(gemm_mma_kernel,
                         cudaFuncAttributeMaxDynamicSharedMemorySize, GEMM_DSMEM);
    cudaFuncSetAttribute(attn_mma_kernel,
                         cudaFuncAttributeMaxDynamicSharedMemorySize, ATTN_DSMEM);

    // 1. instance norm (fp32 exact)
    norm_kernel<<<BATCH, 1024>>>(x, xn);
    // 2. weight transpose -> bf16
    conv_w_kernel<<<768, 256>>>(W_qkv, W_out, wqT, woT);
    // 3. patch embedding (fp32 compute, bf16 out)
    embed_kernel<<<ROWS_TOTAL / 128, 256>>>(xn, W_proj, b_proj, hbf);
    // 4. QKV GEMM (mma.sync): routes to q/k/v bf16 row-major
    gemm_mma_kernel<<<dim3(ROWS_TOTAL / 128, 6), 256, GEMM_DSMEM>>>(
        hbf, wqT, b_qkv, qbf, kbf, vbf, (float*)nullptr, 1);
    // 5. causal flash attention (mma.sync)
    attn_mma_kernel<<<dim3(TPATCH / 128, BATCH), 256, ATTN_DSMEM>>>(
        qbf, kbf, vbf, abf);
    // 6. out projection (mma.sync, fp32 out)
    gemm_mma_kernel<<<dim3(ROWS_TOTAL / 128, 2), 256, GEMM_DSMEM>>>(
        abf, woT, b_out, (__nv_bfloat16*)nullptr, (__nv_bfloat16*)nullptr,
        (__nv_bfloat16*)nullptr, o2, 0);
    // 7. head + loss partials (fp32 exact)
    head_loss_kernel<<<ROWS_TOTAL / 8, 256>>>(o2, W_head, b_head, xn, parts);
    // 8. final scalar
    final_reduce_kernel<<<1, 1024>>>(parts, out);
}

// round 14
// speedup vs baseline: 3.9810x; 1.0581x over previous
#include <cuda_runtime.h>
#include <cuda_bf16.h>
#include <math.h>
#include <stdint.h>

// ---------------------------------------------------------------------------
// Problem constants: B=32, L=32768, PS=32, T=1024, D=256
// ---------------------------------------------------------------------------
#define BATCH 32
#define LSEQ  32768
#define PS    32
#define TPATCH 1024
#define DMODEL 256
#define ROWS_TOTAL 32768

// attention smem row stride (264 bf16 = 132 words ≡ 4 mod 32: conflict-free)
#define AKST 264
// gemm chunk tile stride: 64 cols + 8 pad (36 words ≡ 4 mod 32)
#define GST 72
#define G_STAGE (128 * GST)          // bf16 elems per tile

// ---------------------------------------------------------------------------
// Static device scratch
// ---------------------------------------------------------------------------
__device__ float         g_xnorm[BATCH * LSEQ];           // 4 MB fp32
__device__ float         g_nstats[32 * 8 * 2];
__device__ __nv_bfloat16 g_hbf [ROWS_TOTAL * DMODEL];     // 16 MB
__device__ __nv_bfloat16 g_qbf [ROWS_TOTAL * DMODEL];
__device__ __nv_bfloat16 g_kbf [ROWS_TOTAL * DMODEL];
__device__ __nv_bfloat16 g_vbf [ROWS_TOTAL * DMODEL];
__device__ __nv_bfloat16 g_abf [ROWS_TOTAL * DMODEL];     // attn out
__device__ __nv_bfloat16 g_wqkvT[768 * 256];              // W_qkv^T bf16 [n][k]
__device__ __nv_bfloat16 g_woutT[256 * 256];              // W_out^T bf16 [n][k]
__device__ float         g_out2[ROWS_TOTAL * DMODEL];     // 32 MB fp32
__device__ float         g_partials[4096];

// ---------------------------------------------------------------------------
// Base-ISA helpers: mma.sync m16n8k16 bf16 + ldmatrix + cp.async (sm_80+ PTX)
// ---------------------------------------------------------------------------
__device__ __forceinline__ uint32_t smem_u32(const void* p) {
    uint32_t a;
    asm("{ .reg .u64 t; cvta.to.shared.u64 t, %1; cvt.u32.u64 %0, t; }"
        : "=r"(a) : "l"(p));
    return a;
}

__device__ __forceinline__ void mma_bf16(float d[4], const uint32_t a[4],
                                         const uint32_t b[2]) {
    asm volatile(
        "mma.sync.aligned.m16n8k16.row.col.f32.bf16.bf16.f32 "
        "{%0,%1,%2,%3}, {%4,%5,%6,%7}, {%8,%9}, {%0,%1,%2,%3};"
        : "+f"(d[0]), "+f"(d[1]), "+f"(d[2]), "+f"(d[3])
        : "r"(a[0]), "r"(a[1]), "r"(a[2]), "r"(a[3]), "r"(b[0]), "r"(b[1]));
}

__device__ __forceinline__ void ldmx4(uint32_t r[4], uint32_t addr) {
    asm volatile("ldmatrix.sync.aligned.m8n8.x4.shared.b16 {%0,%1,%2,%3}, [%4];"
        : "=r"(r[0]), "=r"(r[1]), "=r"(r[2]), "=r"(r[3]) : "r"(addr));
}
__device__ __forceinline__ void ldmx4t(uint32_t r[4], uint32_t addr) {
    asm volatile("ldmatrix.sync.aligned.m8n8.x4.trans.shared.b16 {%0,%1,%2,%3}, [%4];"
        : "=r"(r[0]), "=r"(r[1]), "=r"(r[2]), "=r"(r[3]) : "r"(addr));
}

#define CPA16(dst, src) \
    asm volatile("cp.async.cg.shared.global [%0], [%1], 16;" \
                 :: "r"(dst), "l"(src) : "memory")
#define CPC()  asm volatile("cp.async.commit_group;" ::: "memory")
#define CPW0() asm volatile("cp.async.wait_group 0;" ::: "memory")
#define CPW1() asm volatile("cp.async.wait_group 1;" ::: "memory")

__device__ __forceinline__ uint32_t pack_bf16x2(float a, float b) {
    __nv_bfloat162 h = __floats2bfloat162_rn(a, b);
    return *reinterpret_cast<uint32_t*>(&h);
}

// ---------------------------------------------------------------------------
// Kernel 1a/1b: instance norm (ddof=1) split into stats + apply (256 blocks)
// ---------------------------------------------------------------------------
__global__ void __launch_bounds__(256) norm_stat_kernel(
    const float* __restrict__ x, float* __restrict__ stats)
{
    __shared__ float s1[8], s2[8];
    const int b = blockIdx.x >> 3, seg = blockIdx.x & 7;
    const int tid = threadIdx.x, lane = tid & 31, w = tid >> 5;
    const float* xb = x + (size_t)b * LSEQ + seg * 4096;
    float sum = 0.f, sq = 0.f;
#pragma unroll
    for (int u = 0; u < 4; ++u) {
        float4 t = *(const float4*)(xb + tid * 16 + u * 4);
        sum += t.x + t.y + t.z + t.w;
        sq  += t.x * t.x + t.y * t.y + t.z * t.z + t.w * t.w;
    }
#pragma unroll
    for (int off = 16; off > 0; off >>= 1) {
        sum += __shfl_xor_sync(0xffffffffu, sum, off);
        sq  += __shfl_xor_sync(0xffffffffu, sq,  off);
    }
    if (lane == 0) { s1[w] = sum; s2[w] = sq; }
    __syncthreads();
    if (tid == 0) {
        float S = 0.f, Q = 0.f;
#pragma unroll
        for (int i = 0; i < 8; ++i) { S += s1[i]; Q += s2[i]; }
        stats[(b * 8 + seg) * 2]     = S;
        stats[(b * 8 + seg) * 2 + 1] = Q;
    }
}

__global__ void __launch_bounds__(256) norm_apply_kernel(
    const float* __restrict__ x, const float* __restrict__ stats,
    float* __restrict__ xn)
{
    const int b = blockIdx.x >> 3, seg = blockIdx.x & 7;
    const int tid = threadIdx.x;
    float S = 0.f, Q = 0.f;
#pragma unroll
    for (int i = 0; i < 8; ++i) {
        S += stats[(b * 8 + i) * 2];
        Q += stats[(b * 8 + i) * 2 + 1];
    }
    const float mean = S * (1.0f / (float)LSEQ);
    const float var  = (Q - (float)LSEQ * mean * mean) * (1.0f / (float)(LSEQ - 1));
    const float inv  = 1.0f / (sqrtf(var) + 1e-5f);
    const float* xb = x  + (size_t)b * LSEQ + seg * 4096;
    float*       xo = xn + (size_t)b * LSEQ + seg * 4096;
#pragma unroll
    for (int u = 0; u < 4; ++u) {
        float4 t = *(const float4*)(xb + tid * 16 + u * 4);
        t.x = (t.x - mean) * inv; t.y = (t.y - mean) * inv;
        t.z = (t.z - mean) * inv; t.w = (t.w - mean) * inv;
        *(float4*)(xo + tid * 16 + u * 4) = t;
    }
}

// ---------------------------------------------------------------------------
// Kernel 2: transpose+convert weights to bf16 [N,K]
// ---------------------------------------------------------------------------
__global__ void __launch_bounds__(256) conv_w_kernel(
    const float* __restrict__ Wq, const float* __restrict__ Wo,
    __nv_bfloat16* __restrict__ WqT, __nv_bfloat16* __restrict__ WoT)
{
    int i = blockIdx.x * 256 + threadIdx.x;
    if (i < 768 * 256) {
        int n = i >> 8, k = i & 255;
        WqT[i] = __float2bfloat16(Wq[k * 768 + n]);
    }
    if (i < 256 * 256) {
        int n = i >> 8, k = i & 255;
        WoT[i] = __float2bfloat16(Wo[k * 256 + n]);
    }
}

// ---------------------------------------------------------------------------
// Kernel 3: patch embedding (exact fp32 compute, bf16 output)
// ---------------------------------------------------------------------------
__global__ void __launch_bounds__(256) embed_kernel(
    const float* __restrict__ xn, const float* __restrict__ Wp,
    const float* __restrict__ bp, __nv_bfloat16* __restrict__ hbf)
{
    __shared__ float ps[128 * 32];
    const int tid = threadIdx.x;
    const int m0 = blockIdx.x * 128;
    const float* src = xn + (size_t)m0 * 32;
#pragma unroll
    for (int it = 0; it < 4; ++it)
        *(float4*)&ps[(tid + it * 256) * 4] = *(const float4*)(src + (tid + it * 256) * 4);
    __syncthreads();

    float w[32];
#pragma unroll
    for (int k = 0; k < 32; ++k) w[k] = Wp[k * 256 + tid];
    const float bias = bp[tid];

    for (int r = 0; r < 128; ++r) {
        float acc = bias;
#pragma unroll
        for (int k = 0; k < 32; ++k) acc += ps[r * 32 + k] * w[k];
        hbf[(size_t)(m0 + r) * 256 + tid] = __float2bfloat16(acc);
    }
}

// ---------------------------------------------------------------------------
// Kernel 4: pipelined mma.sync bf16 GEMM.
// C[128,128] = A[m0..,:256] @ Wt[n0..,:256]^T, BK=64, 3-stage cp.async.
// 8 warps 4(m)x2(n), warp tile 32x64.  smem 110.6KB -> 2 CTAs/SM.
// mode 1: route cols to q/k/v bf16.  mode 0: fp32 out.
// ---------------------------------------------------------------------------
#define GEMM_DSMEM (3 * 2 * G_STAGE * 2)

__global__ void __launch_bounds__(256) gemm_mma_kernel(
    const __nv_bfloat16* __restrict__ A,
    const __nv_bfloat16* __restrict__ Wt,
    const float* __restrict__ bias,
    __nv_bfloat16* qout, __nv_bfloat16* kout, __nv_bfloat16* vout,
    float* fout, int mode)
{
    extern __shared__ __nv_bfloat16 sm[];
    const uint32_t smb = smem_u32(sm);

    const int tid = threadIdx.x, wid = tid >> 5, lane = tid & 31;
    const int m0 = blockIdx.x * 128, n0 = blockIdx.y * 128;
    const int wm = wid & 3, wn = wid >> 2;

    const int lr = lane & 7, lg = lane >> 3;
    const int a_ro = lr + (lg & 1) * 8, a_co = (lg >> 1) * 8;
    const int b_ro = lr + (lg >> 1) * 8, b_co = (lg & 1) * 8;

    const __nv_bfloat16* Ab = A + (size_t)m0 * 256;
    const __nv_bfloat16* Bb = Wt + (size_t)n0 * 256;

    // per-thread load coords: f = tid + it*256 -> row = f>>3, c16 = f&7
    auto ISSUE = [&](int c, int s) {
        const uint32_t sa = smb + (uint32_t)s * (2 * G_STAGE * 2);
        const uint32_t sb = sa + G_STAGE * 2;
#pragma unroll
        for (int it = 0; it < 4; ++it) {
            int f = tid + it * 256;
            int row = f >> 3, c16 = f & 7;
            uint32_t off = (uint32_t)(row * GST + c16 * 8) * 2;
            CPA16(sa + off, Ab + (size_t)row * 256 + c * 64 + c16 * 8);
            CPA16(sb + off, Bb + (size_t)row * 256 + c * 64 + c16 * 8);
        }
    };

    float O[2][8][4];
#pragma unroll
    for (int mi = 0; mi < 2; ++mi)
#pragma unroll
        for (int ni = 0; ni < 8; ++ni)
#pragma unroll
            for (int c = 0; c < 4; ++c) O[mi][ni][c] = 0.f;

    auto COMP = [&](int s) {
        const uint32_t sa = smb + (uint32_t)s * (2 * G_STAGE * 2);
        const uint32_t abase = sa + ((wm * 32 + a_ro) * GST + a_co) * 2;
        const uint32_t bbase = sa + G_STAGE * 2 + ((wn * 64 + b_ro) * GST + b_co) * 2;
#pragma unroll
        for (int kc = 0; kc < 4; ++kc) {
            uint32_t Af[2][4];
            ldmx4(Af[0], abase + kc * 32);
            ldmx4(Af[1], abase + 16 * GST * 2 + kc * 32);
#pragma unroll
            for (int t = 0; t < 4; ++t) {
                uint32_t Bf[4];
                ldmx4(Bf, bbase + t * 16 * GST * 2 + kc * 32);
                mma_bf16(O[0][2 * t],     Af[0], Bf);
                mma_bf16(O[0][2 * t + 1], Af[0], Bf + 2);
                mma_bf16(O[1][2 * t],     Af[1], Bf);
                mma_bf16(O[1][2 * t + 1], Af[1], Bf + 2);
            }
        }
    };

    ISSUE(0, 0); CPC();
    ISSUE(1, 1); CPC();
#pragma unroll
    for (int c = 0; c < 4; ++c) {
        if (c < 3) { CPW1(); } else { CPW0(); }
        __syncthreads();
        if (c + 2 < 4) { ISSUE(c + 2, (c + 2) % 3); CPC(); }
        COMP(c % 3);
        __syncthreads();
    }

    // epilogue
#pragma unroll
    for (int mi = 0; mi < 2; ++mi) {
        const int r0 = m0 + wm * 32 + mi * 16 + (lane >> 2);
        const int r1 = r0 + 8;
#pragma unroll
        for (int ni = 0; ni < 8; ++ni) {
            const int cg = n0 + wn * 64 + ni * 8 + (lane & 3) * 2;
            const float b0 = bias[cg], b1 = bias[cg + 1];
            if (mode == 0) {
                float2 v0 = make_float2(O[mi][ni][0] + b0, O[mi][ni][1] + b1);
                float2 v1 = make_float2(O[mi][ni][2] + b0, O[mi][ni][3] + b1);
                *(float2*)(fout + (size_t)r0 * 256 + cg) = v0;
                *(float2*)(fout + (size_t)r1 * 256 + cg) = v1;
            } else {
                __nv_bfloat16* base = (cg < 256) ? qout : (cg < 512) ? kout : vout;
                const int cc = cg & 255;
                *(uint32_t*)(base + (size_t)r0 * 256 + cc) =
                    pack_bf16x2(O[mi][ni][0] + b0, O[mi][ni][1] + b1);
                *(uint32_t*)(base + (size_t)r1 * 256 + cc) =
                    pack_bf16x2(O[mi][ni][2] + b0, O[mi][ni][3] + b1);
            }
        }
    }
}

// ---------------------------------------------------------------------------
// Kernel 5: causal flash attention, mma.sync + double-buffered cp.async K/V.
// Block = (b, q-tile 128).  K/V tiles of 64 keys, 2 stages.
// Q resident; S = Q K^T; no-max softmax; P in regs; O += P V (ldmatrix.trans).
// smem: Q 128xAKST | 2 x (K 64xAKST + V 64xAKST) = 202.8 KB.
// ---------------------------------------------------------------------------
#define ATTN_DSMEM ((128 * AKST + 4 * 64 * AKST) * 2)

__global__ void __launch_bounds__(256, 1) attn_mma_kernel(
    const __nv_bfloat16* __restrict__ qg,
    const __nv_bfloat16* __restrict__ kg,
    const __nv_bfloat16* __restrict__ vg,
    __nv_bfloat16* __restrict__ og)
{
    extern __shared__ __nv_bfloat16 sm[];
    const uint32_t smb = smem_u32(sm);
    const uint32_t QB = 128 * AKST * 2;          // Q bytes
    const uint32_t TB = 64 * AKST * 2;           // one K or V tile bytes

    const int tid = threadIdx.x, wid = tid >> 5, lane = tid & 31;
    const int b = blockIdx.y;
    const int qt = 7 - (int)blockIdx.x;          // heavy tiles first
    const int q0 = qt * 128;
    const int m0 = wid * 16;
    const int m0g = q0 + m0;                     // warp's first q row (global)

    const int lr = lane & 7, lg = lane >> 3;
    const int a_ro = lr + (lg & 1) * 8, a_co = (lg >> 1) * 8;
    const int b_ro = lr + (lg >> 1) * 8, b_co = (lg & 1) * 8;

    // load Q tile (plain loads, once)
    const __nv_bfloat16* qb = qg + (size_t)(b * TPATCH + q0) * 256;
#pragma unroll
    for (int it = 0; it < 16; ++it) {
        int f = tid + it * 256;
        int row = f >> 5, c16 = f & 31;
        *(uint4*)(sm + row * AKST + c16 * 8) =
            *(const uint4*)(qb + (size_t)row * 256 + c16 * 8);
    }

    const int ntiles = 2 * qt + 2;
    auto ISSUEKV = [&](int t, int s) {
        const __nv_bfloat16* kb = kg + (size_t)(b * TPATCH + t * 64) * 256;
        const __nv_bfloat16* vb = vg + (size_t)(b * TPATCH + t * 64) * 256;
        const uint32_t ks = smb + QB + (uint32_t)s * 2 * TB;
        const uint32_t vs = ks + TB;
#pragma unroll
        for (int it = 0; it < 8; ++it) {
            int f = tid + it * 256;
            int row = f >> 5, c16 = f & 31;
            uint32_t off = (uint32_t)(row * AKST + c16 * 8) * 2;
            CPA16(ks + off, kb + (size_t)row * 256 + c16 * 8);
            CPA16(vs + off, vb + (size_t)row * 256 + c16 * 8);
        }
    };

    ISSUEKV(0, 0); CPC();
    __syncthreads();   // Q visible to all warps

    // cache Q fragments
    uint32_t Qf[16][4];
    {
        const uint32_t qbase = smb + ((m0 + a_ro) * AKST + a_co) * 2;
#pragma unroll
        for (int kc = 0; kc < 16; ++kc) ldmx4(Qf[kc], qbase + kc * 32);
    }

    float O[32][4];
#pragma unroll
    for (int i = 0; i < 32; ++i)
#pragma unroll
        for (int c = 0; c < 4; ++c) O[i][c] = 0.f;
    float l0 = 0.f, l1 = 0.f;

    const float cexp = 0.0625f * 1.4426950408889634f;   // 1/16 * log2(e)
    const int row0g = m0g + (lane >> 2);
    const int row1g = row0g + 8;

    for (int kt = 0; kt < ntiles; ++kt) {
        if (kt + 1 < ntiles) { ISSUEKV(kt + 1, (kt + 1) & 1); CPC(); CPW1(); }
        else                 { CPW0(); }
        __syncthreads();

        const int k0 = kt * 64;
        const uint32_t ks = smb + QB + (uint32_t)(kt & 1) * 2 * TB;
        const uint32_t vs = ks + TB;

#pragma unroll
        for (int j = 0; j < 4; ++j) {
            const int koff = k0 + 16 * j;
            if (koff > m0g + 15) break;          // fully masked (warp-uniform)

            // ---- S = Q K^T for 16 keys ----
            float s0[4] = {0.f, 0.f, 0.f, 0.f};
            float s1[4] = {0.f, 0.f, 0.f, 0.f};
            const uint32_t bbase = ks + ((16 * j + b_ro) * AKST + b_co) * 2;
#pragma unroll
            for (int kc = 0; kc < 16; ++kc) {
                uint32_t Bf[4];
                ldmx4(Bf, bbase + kc * 32);
                mma_bf16(s0, Qf[kc], Bf);
                mma_bf16(s1, Qf[kc], Bf + 2);
            }

            // ---- softmax (no max subtraction) + causal mask ----
            float p0[4], p1[4];
#pragma unroll
            for (int c = 0; c < 4; ++c) {
                p0[c] = exp2f(s0[c] * cexp);
                p1[c] = exp2f(s1[c] * cexp);
            }
            if (koff + 15 > m0g) {               // block touches the diagonal
                const int c0g = koff + (lane & 3) * 2;
                if (c0g > row0g)     p0[0] = 0.f;
                if (c0g + 1 > row0g) p0[1] = 0.f;
                if (c0g > row1g)     p0[2] = 0.f;
                if (c0g + 1 > row1g) p0[3] = 0.f;
                if (c0g + 8 > row0g) p1[0] = 0.f;
                if (c0g + 9 > row0g) p1[1] = 0.f;
                if (c0g + 8 > row1g) p1[2] = 0.f;
                if (c0g + 9 > row1g) p1[3] = 0.f;
            }
            l0 += p0[0] + p0[1] + p1[0] + p1[1];
            l1 += p0[2] + p0[3] + p1[2] + p1[3];

            uint32_t P[4];
            P[0] = pack_bf16x2(p0[0], p0[1]);
            P[1] = pack_bf16x2(p0[2], p0[3]);
            P[2] = pack_bf16x2(p1[0], p1[1]);
            P[3] = pack_bf16x2(p1[2], p1[3]);

            // ---- O += P V (V row-major, trans ldmatrix) ----
            const uint32_t vbase = vs + ((16 * j + a_ro) * AKST + a_co) * 2;
#pragma unroll
            for (int dt = 0; dt < 16; ++dt) {
                uint32_t Vf[4];
                ldmx4t(Vf, vbase + dt * 32);
                mma_bf16(O[2 * dt],     P, Vf);
                mma_bf16(O[2 * dt + 1], P, Vf + 2);
            }
        }
        __syncthreads();
    }

    // ---- finalize ----
    l0 += __shfl_xor_sync(0xffffffffu, l0, 1);
    l0 += __shfl_xor_sync(0xffffffffu, l0, 2);
    l1 += __shfl_xor_sync(0xffffffffu, l1, 1);
    l1 += __shfl_xor_sync(0xffffffffu, l1, 2);
    const float inv0 = 1.0f / l0, inv1 = 1.0f / l1;

    __nv_bfloat16* o0 = og + (size_t)(b * TPATCH + row0g) * 256;
    __nv_bfloat16* o1 = og + (size_t)(b * TPATCH + row1g) * 256;
#pragma unroll
    for (int i = 0; i < 32; ++i) {
        const int d0 = i * 8 + (lane & 3) * 2;
        *(uint32_t*)(o0 + d0) = pack_bf16x2(O[i][0] * inv0, O[i][1] * inv0);
        *(uint32_t*)(o1 + d0) = pack_bf16x2(O[i][2] * inv1, O[i][3] * inv1);
    }
}

// ---------------------------------------------------------------------------
// Kernel 6: head GEMM (256->32) fused with next-patch MSE partials (fp32)
// ---------------------------------------------------------------------------
__global__ void __launch_bounds__(256) head_loss_kernel(
    const float* __restrict__ X, const float* __restrict__ Wh,
    const float* __restrict__ bh, const float* __restrict__ xn,
    float* __restrict__ partials)
{
    __shared__ float Ws[256 * 32];
    __shared__ float wsum[8];
    const int tid = threadIdx.x, lane = tid & 31, w = tid >> 5;

    for (int idx = tid; idx < 256 * 32; idx += 256) Ws[idx] = Wh[idx];
    __syncthreads();

    const int row = blockIdx.x * 8 + w;
    const float* xr = X + (size_t)row * 256;
    float r[8];
#pragma unroll
    for (int k8 = 0; k8 < 8; ++k8) r[k8] = xr[k8 * 32 + lane];

    float acc = 0.f;
#pragma unroll
    for (int k8 = 0; k8 < 8; ++k8)
#pragma unroll
        for (int ll = 0; ll < 32; ++ll) {
            float v = __shfl_sync(0xffffffffu, r[k8], ll);
            acc += v * Ws[(k8 * 32 + ll) * 32 + lane];
        }

    const int bidx = row >> 10, t = row & 1023;
    float sq = 0.f;
    if (t < TPATCH - 1) {
        float pred = acc + bh[lane];
        float tgt = xn[(size_t)bidx * LSEQ + (t + 1) * 32 + lane];
        float d = pred - tgt;
        sq = d * d;
    }
#pragma unroll
    for (int off = 16; off > 0; off >>= 1)
        sq += __shfl_xor_sync(0xffffffffu, sq, off);
    if (lane == 0) wsum[w] = sq;
    __syncthreads();
    if (tid == 0) {
        float s = 0.f;
#pragma unroll
        for (int u = 0; u < 8; ++u) s += wsum[u];
        partials[blockIdx.x] = s;
    }
}

__global__ void __launch_bounds__(1024) final_reduce_kernel(
    const float* __restrict__ partials, float* __restrict__ out)
{
    __shared__ float sm2[1024];
    const int tid = threadIdx.x;
    float s = 0.f;
    for (int idx = tid; idx < 4096; idx += 1024) s += partials[idx];
    sm2[tid] = s;
    __syncthreads();
    for (int st = 512; st > 0; st >>= 1) {
        if (tid < st) sm2[tid] += sm2[tid + st];
        __syncthreads();
    }
    if (tid == 0)
        out[0] = sm2[0] / (float)(BATCH * (TPATCH - 1) * PS);
}

// ---------------------------------------------------------------------------
// Launch
// ---------------------------------------------------------------------------
extern "C" void kernel_launch(void* const* d_in, const int* in_sizes, int n_in,
                              void* d_out, int out_size)
{
    const float* x      = (const float*)d_in[0];
    const float* W_proj = (const float*)d_in[1];
    const float* b_proj = (const float*)d_in[2];
    const float* W_qkv  = (const float*)d_in[3];
    const float* b_qkv  = (const float*)d_in[4];
    const float* W_out  = (const float*)d_in[5];
    const float* b_out  = (const float*)d_in[6];
    const float* W_head = (const float*)d_in[7];
    const float* b_head = (const float*)d_in[8];
    float* out = (float*)d_out;

    float *xn, *nst, *o2, *parts;
    __nv_bfloat16 *hbf, *qbf, *kbf, *vbf, *abf, *wqT, *woT;
    cudaGetSymbolAddress((void**)&xn,   g_xnorm);
    cudaGetSymbolAddress((void**)&nst,  g_nstats);
    cudaGetSymbolAddress((void**)&hbf,  g_hbf);
    cudaGetSymbolAddress((void**)&qbf,  g_qbf);
    cudaGetSymbolAddress((void**)&kbf,  g_kbf);
    cudaGetSymbolAddress((void**)&vbf,  g_vbf);
    cudaGetSymbolAddress((void**)&abf,  g_abf);
    cudaGetSymbolAddress((void**)&wqT,  g_wqkvT);
    cudaGetSymbolAddress((void**)&woT,  g_woutT);
    cudaGetSymbolAddress((void**)&o2,   g_out2);
    cudaGetSymbolAddress((void**)&parts, g_partials);

    cudaFuncSetAttribute(gemm_mma_kernel,
                         cudaFuncAttributeMaxDynamicSharedMemorySize, GEMM_DSMEM);
    cudaFuncSetAttribute(attn_mma_kernel,
                         cudaFuncAttributeMaxDynamicSharedMemorySize, ATTN_DSMEM);

    // 1. instance norm (fp32 exact, two-stage, 256 blocks)
    norm_stat_kernel<<<256, 256>>>(x, nst);
    norm_apply_kernel<<<256, 256>>>(x, nst, xn);
    // 2. weight transpose -> bf16
    conv_w_kernel<<<768, 256>>>(W_qkv, W_out, wqT, woT);
    // 3. patch embedding (fp32 compute, bf16 out)
    embed_kernel<<<ROWS_TOTAL / 128, 256>>>(xn, W_proj, b_proj, hbf);
    // 4. QKV GEMM (pipelined mma.sync)
    gemm_mma_kernel<<<dim3(ROWS_TOTAL / 128, 6), 256, GEMM_DSMEM>>>(
        hbf, wqT, b_qkv, qbf, kbf, vbf, (float*)nullptr, 1);
    // 5. causal flash attention (mma.sync, double-buffered K/V)
    attn_mma_kernel<<<dim3(TPATCH / 128, BATCH), 256, ATTN_DSMEM>>>(
        qbf, kbf, vbf, abf);
    // 6. out projection (pipelined mma.sync, fp32 out)
    gemm_mma_kernel<<<dim3(ROWS_TOTAL / 128, 2), 256, GEMM_DSMEM>>>(
        abf, woT, b_out, (__nv_bfloat16*)nullptr, (__nv_bfloat16*)nullptr,
        (__nv_bfloat16*)nullptr, o2, 0);
    // 7. head + loss partials (fp32 exact)
    head_loss_kernel<<<ROWS_TOTAL / 8, 256>>>(o2, W_head, b_head, xn, parts);
    // 8. final scalar
    final_reduce_kernel<<<1, 1024>>>(parts, out);
}

// round 17
// speedup vs baseline: 5.3455x; 1.3427x over previous
#include <cuda_runtime.h>
#include <cuda_bf16.h>
#include <math.h>
#include <stdint.h>

// ---------------------------------------------------------------------------
// Problem constants: B=32, L=32768, PS=32, T=1024, D=256
// ---------------------------------------------------------------------------
#define BATCH 32
#define LSEQ  32768
#define PS    32
#define TPATCH 1024
#define DMODEL 256
#define ROWS_TOTAL 32768

// attention smem row stride (264 bf16 = 132 words ≡ 4 mod 32: conflict-free)
#define AKST 264
// gemm chunk tile stride: 64 cols + 8 pad (36 words ≡ 4 mod 32)
#define GST 72
#define G_STAGE (128 * GST)          // bf16 elems per tile

// ---------------------------------------------------------------------------
// Static device scratch
// ---------------------------------------------------------------------------
__device__ float         g_nstats[32 * 8 * 2];
__device__ __nv_bfloat16 g_hbf [ROWS_TOTAL * DMODEL];     // 16 MB
__device__ __nv_bfloat16 g_qbf [ROWS_TOTAL * DMODEL];
__device__ __nv_bfloat16 g_kbf [ROWS_TOTAL * DMODEL];
__device__ __nv_bfloat16 g_vbf [ROWS_TOTAL * DMODEL];
__device__ __nv_bfloat16 g_abf [ROWS_TOTAL * DMODEL];     // attn out
__device__ __nv_bfloat16 g_wqkvT[768 * 256];              // W_qkv^T bf16 [n][k]
__device__ __nv_bfloat16 g_woutT[256 * 256];              // W_out^T bf16 [n][k]
__device__ __nv_bfloat16 g_wheadT[32 * 256];              // W_head^T bf16 [n][k]
__device__ float         g_partials[4096];

// ---------------------------------------------------------------------------
// Base-ISA helpers: mma.sync m16n8k16 bf16 + ldmatrix + cp.async (sm_80+ PTX)
// ---------------------------------------------------------------------------
__device__ __forceinline__ uint32_t smem_u32(const void* p) {
    uint32_t a;
    asm("{ .reg .u64 t; cvta.to.shared.u64 t, %1; cvt.u32.u64 %0, t; }"
        : "=r"(a) : "l"(p));
    return a;
}

__device__ __forceinline__ void mma_bf16(float d[4], const uint32_t a[4],
                                         const uint32_t b[2]) {
    asm volatile(
        "mma.sync.aligned.m16n8k16.row.col.f32.bf16.bf16.f32 "
        "{%0,%1,%2,%3}, {%4,%5,%6,%7}, {%8,%9}, {%0,%1,%2,%3};"
        : "+f"(d[0]), "+f"(d[1]), "+f"(d[2]), "+f"(d[3])
        : "r"(a[0]), "r"(a[1]), "r"(a[2]), "r"(a[3]), "r"(b[0]), "r"(b[1]));
}

__device__ __forceinline__ void ldmx4(uint32_t r[4], uint32_t addr) {
    asm volatile("ldmatrix.sync.aligned.m8n8.x4.shared.b16 {%0,%1,%2,%3}, [%4];"
        : "=r"(r[0]), "=r"(r[1]), "=r"(r[2]), "=r"(r[3]) : "r"(addr));
}
__device__ __forceinline__ void ldmx4t(uint32_t r[4], uint32_t addr) {
    asm volatile("ldmatrix.sync.aligned.m8n8.x4.trans.shared.b16 {%0,%1,%2,%3}, [%4];"
        : "=r"(r[0]), "=r"(r[1]), "=r"(r[2]), "=r"(r[3]) : "r"(addr));
}

#define CPA16(dst, src) \
    asm volatile("cp.async.cg.shared.global [%0], [%1], 16;" \
                 :: "r"(dst), "l"(src) : "memory")
#define CPC()  asm volatile("cp.async.commit_group;" ::: "memory")
#define CPW0() asm volatile("cp.async.wait_group 0;" ::: "memory")
#define CPW1() asm volatile("cp.async.wait_group 1;" ::: "memory")

__device__ __forceinline__ uint32_t pack_bf16x2(float a, float b) {
    __nv_bfloat162 h = __floats2bfloat162_rn(a, b);
    return *reinterpret_cast<uint32_t*>(&h);
}

// ---------------------------------------------------------------------------
// Kernel 1: instance norm stats (ddof=1 handled at consumers), 256 blocks
// ---------------------------------------------------------------------------
__global__ void __launch_bounds__(256) norm_stat_kernel(
    const float* __restrict__ x, float* __restrict__ stats)
{
    __shared__ float s1[8], s2[8];
    const int b = blockIdx.x >> 3, seg = blockIdx.x & 7;
    const int tid = threadIdx.x, lane = tid & 31, w = tid >> 5;
    const float* xb = x + (size_t)b * LSEQ + seg * 4096;
    float sum = 0.f, sq = 0.f;
#pragma unroll
    for (int u = 0; u < 4; ++u) {
        float4 t = *(const float4*)(xb + tid * 16 + u * 4);
        sum += t.x + t.y + t.z + t.w;
        sq  += t.x * t.x + t.y * t.y + t.z * t.z + t.w * t.w;
    }
#pragma unroll
    for (int off = 16; off > 0; off >>= 1) {
        sum += __shfl_xor_sync(0xffffffffu, sum, off);
        sq  += __shfl_xor_sync(0xffffffffu, sq,  off);
    }
    if (lane == 0) { s1[w] = sum; s2[w] = sq; }
    __syncthreads();
    if (tid == 0) {
        float S = 0.f, Q = 0.f;
#pragma unroll
        for (int i = 0; i < 8; ++i) { S += s1[i]; Q += s2[i]; }
        stats[(b * 8 + seg) * 2]     = S;
        stats[(b * 8 + seg) * 2 + 1] = Q;
    }
}

// mean / inv-std for batch b from segment stats (deterministic fixed order)
__device__ __forceinline__ void batch_norm_params(
    const float* __restrict__ stats, int b, float& mean, float& inv)
{
    float S = 0.f, Q = 0.f;
#pragma unroll
    for (int i = 0; i < 8; ++i) {
        S += stats[(b * 8 + i) * 2];
        Q += stats[(b * 8 + i) * 2 + 1];
    }
    mean = S * (1.0f / (float)LSEQ);
    const float var = (Q - (float)LSEQ * mean * mean) * (1.0f / (float)(LSEQ - 1));
    inv = 1.0f / (sqrtf(var) + 1e-5f);
}

// ---------------------------------------------------------------------------
// Kernel 2: transpose+convert weights to bf16 [N,K]
// ---------------------------------------------------------------------------
__global__ void __launch_bounds__(256) conv_w_kernel(
    const float* __restrict__ Wq, const float* __restrict__ Wo,
    const float* __restrict__ Wh,
    __nv_bfloat16* __restrict__ WqT, __nv_bfloat16* __restrict__ WoT,
    __nv_bfloat16* __restrict__ WhT)
{
    int i = blockIdx.x * 256 + threadIdx.x;
    if (i < 768 * 256) {
        int n = i >> 8, k = i & 255;
        WqT[i] = __float2bfloat16(Wq[k * 768 + n]);
    }
    if (i < 256 * 256) {
        int n = i >> 8, k = i & 255;
        WoT[i] = __float2bfloat16(Wo[k * 256 + n]);
    }
    if (i < 32 * 256) {
        int n = i >> 8, k = i & 255;
        WhT[i] = __float2bfloat16(Wh[k * 32 + n]);
    }
}

// ---------------------------------------------------------------------------
// Kernel 3: patch embedding, normalization fused, 4-row ILP, 512 blocks
// ---------------------------------------------------------------------------
__global__ void __launch_bounds__(256) embed_kernel(
    const float* __restrict__ x, const float* __restrict__ stats,
    const float* __restrict__ Wp, const float* __restrict__ bp,
    __nv_bfloat16* __restrict__ hbf)
{
    __shared__ float ps[64 * 32];
    const int tid = threadIdx.x;
    const int m0 = blockIdx.x * 64;          // 64 patch rows, within one batch
    const int b = m0 >> 10;
    float mean, inv;
    batch_norm_params(stats, b, mean, inv);

    const float* src = x + (size_t)m0 * 32;
#pragma unroll
    for (int it = 0; it < 2; ++it) {
        int idx = (tid + it * 256) * 4;
        float4 t = *(const float4*)(src + idx);
        t.x = (t.x - mean) * inv; t.y = (t.y - mean) * inv;
        t.z = (t.z - mean) * inv; t.w = (t.w - mean) * inv;
        *(float4*)&ps[idx] = t;
    }
    __syncthreads();

    float w[32];
#pragma unroll
    for (int k = 0; k < 32; ++k) w[k] = Wp[k * 256 + tid];
    const float bias = bp[tid];

    for (int r0 = 0; r0 < 64; r0 += 4) {
        float a0 = bias, a1 = bias, a2 = bias, a3 = bias;
#pragma unroll
        for (int k = 0; k < 32; ++k) {
            a0 += ps[(r0 + 0) * 32 + k] * w[k];
            a1 += ps[(r0 + 1) * 32 + k] * w[k];
            a2 += ps[(r0 + 2) * 32 + k] * w[k];
            a3 += ps[(r0 + 3) * 32 + k] * w[k];
        }
        hbf[(size_t)(m0 + r0 + 0) * 256 + tid] = __float2bfloat16(a0);
        hbf[(size_t)(m0 + r0 + 1) * 256 + tid] = __float2bfloat16(a1);
        hbf[(size_t)(m0 + r0 + 2) * 256 + tid] = __float2bfloat16(a2);
        hbf[(size_t)(m0 + r0 + 3) * 256 + tid] = __float2bfloat16(a3);
    }
}

// ---------------------------------------------------------------------------
// Kernel 4: pipelined mma.sync bf16 GEMM (QKV).  BK=64, 3-stage cp.async.
// 8 warps 4(m)x2(n), warp tile 32x64.  Routes cols to q/k/v bf16.
// ---------------------------------------------------------------------------
#define GEMM_DSMEM (3 * 2 * G_STAGE * 2)

__global__ void __launch_bounds__(256) gemm_mma_kernel(
    const __nv_bfloat16* __restrict__ A,
    const __nv_bfloat16* __restrict__ Wt,
    const float* __restrict__ bias,
    __nv_bfloat16* qout, __nv_bfloat16* kout, __nv_bfloat16* vout)
{
    extern __shared__ __nv_bfloat16 sm[];
    const uint32_t smb = smem_u32(sm);

    const int tid = threadIdx.x, wid = tid >> 5, lane = tid & 31;
    const int m0 = blockIdx.x * 128, n0 = blockIdx.y * 128;
    const int wm = wid & 3, wn = wid >> 2;

    const int lr = lane & 7, lg = lane >> 3;
    const int a_ro = lr + (lg & 1) * 8, a_co = (lg >> 1) * 8;
    const int b_ro = lr + (lg >> 1) * 8, b_co = (lg & 1) * 8;

    const __nv_bfloat16* Ab = A + (size_t)m0 * 256;
    const __nv_bfloat16* Bb = Wt + (size_t)n0 * 256;

    auto ISSUE = [&](int c, int s) {
        const uint32_t sa = smb + (uint32_t)s * (2 * G_STAGE * 2);
        const uint32_t sb = sa + G_STAGE * 2;
#pragma unroll
        for (int it = 0; it < 4; ++it) {
            int f = tid + it * 256;
            int row = f >> 3, c16 = f & 7;
            uint32_t off = (uint32_t)(row * GST + c16 * 8) * 2;
            CPA16(sa + off, Ab + (size_t)row * 256 + c * 64 + c16 * 8);
            CPA16(sb + off, Bb + (size_t)row * 256 + c * 64 + c16 * 8);
        }
    };

    float O[2][8][4];
#pragma unroll
    for (int mi = 0; mi < 2; ++mi)
#pragma unroll
        for (int ni = 0; ni < 8; ++ni)
#pragma unroll
            for (int c = 0; c < 4; ++c) O[mi][ni][c] = 0.f;

    auto COMP = [&](int s) {
        const uint32_t sa = smb + (uint32_t)s * (2 * G_STAGE * 2);
        const uint32_t abase = sa + ((wm * 32 + a_ro) * GST + a_co) * 2;
        const uint32_t bbase = sa + G_STAGE * 2 + ((wn * 64 + b_ro) * GST + b_co) * 2;
#pragma unroll
        for (int kc = 0; kc < 4; ++kc) {
            uint32_t Af[2][4];
            ldmx4(Af[0], abase + kc * 32);
            ldmx4(Af[1], abase + 16 * GST * 2 + kc * 32);
#pragma unroll
            for (int t = 0; t < 4; ++t) {
                uint32_t Bf[4];
                ldmx4(Bf, bbase + t * 16 * GST * 2 + kc * 32);
                mma_bf16(O[0][2 * t],     Af[0], Bf);
                mma_bf16(O[0][2 * t + 1], Af[0], Bf + 2);
                mma_bf16(O[1][2 * t],     Af[1], Bf);
                mma_bf16(O[1][2 * t + 1], Af[1], Bf + 2);
            }
        }
    };

    ISSUE(0, 0); CPC();
    ISSUE(1, 1); CPC();
#pragma unroll
    for (int c = 0; c < 4; ++c) {
        if (c < 3) { CPW1(); } else { CPW0(); }
        __syncthreads();
        if (c + 2 < 4) { ISSUE(c + 2, (c + 2) % 3); CPC(); }
        COMP(c % 3);
        __syncthreads();
    }

#pragma unroll
    for (int mi = 0; mi < 2; ++mi) {
        const int r0 = m0 + wm * 32 + mi * 16 + (lane >> 2);
        const int r1 = r0 + 8;
#pragma unroll
        for (int ni = 0; ni < 8; ++ni) {
            const int cg = n0 + wn * 64 + ni * 8 + (lane & 3) * 2;
            const float b0 = bias[cg], b1 = bias[cg + 1];
            __nv_bfloat16* base = (cg < 256) ? qout : (cg < 512) ? kout : vout;
            const int cc = cg & 255;
            *(uint32_t*)(base + (size_t)r0 * 256 + cc) =
                pack_bf16x2(O[mi][ni][0] + b0, O[mi][ni][1] + b1);
            *(uint32_t*)(base + (size_t)r1 * 256 + cc) =
                pack_bf16x2(O[mi][ni][2] + b0, O[mi][ni][3] + b1);
        }
    }
}

// ---------------------------------------------------------------------------
// Kernel 5: causal flash attention, mma.sync + double-buffered cp.async K/V.
// ---------------------------------------------------------------------------
#define ATTN_DSMEM ((128 * AKST + 4 * 64 * AKST) * 2)

__global__ void __launch_bounds__(256, 1) attn_mma_kernel(
    const __nv_bfloat16* __restrict__ qg,
    const __nv_bfloat16* __restrict__ kg,
    const __nv_bfloat16* __restrict__ vg,
    __nv_bfloat16* __restrict__ og)
{
    extern __shared__ __nv_bfloat16 sm[];
    const uint32_t smb = smem_u32(sm);
    const uint32_t QB = 128 * AKST * 2;
    const uint32_t TB = 64 * AKST * 2;

    const int tid = threadIdx.x, wid = tid >> 5, lane = tid & 31;
    const int b = blockIdx.y;
    const int qt = 7 - (int)blockIdx.x;
    const int q0 = qt * 128;
    const int m0 = wid * 16;
    const int m0g = q0 + m0;

    const int lr = lane & 7, lg = lane >> 3;
    const int a_ro = lr + (lg & 1) * 8, a_co = (lg >> 1) * 8;
    const int b_ro = lr + (lg >> 1) * 8, b_co = (lg & 1) * 8;

    const __nv_bfloat16* qb = qg + (size_t)(b * TPATCH + q0) * 256;
#pragma unroll
    for (int it = 0; it < 16; ++it) {
        int f = tid + it * 256;
        int row = f >> 5, c16 = f & 31;
        *(uint4*)(sm + row * AKST + c16 * 8) =
            *(const uint4*)(qb + (size_t)row * 256 + c16 * 8);
    }

    const int ntiles = 2 * qt + 2;
    auto ISSUEKV = [&](int t, int s) {
        const __nv_bfloat16* kb = kg + (size_t)(b * TPATCH + t * 64) * 256;
        const __nv_bfloat16* vb = vg + (size_t)(b * TPATCH + t * 64) * 256;
        const uint32_t ks = smb + QB + (uint32_t)s * 2 * TB;
        const uint32_t vs = ks + TB;
#pragma unroll
        for (int it = 0; it < 8; ++it) {
            int f = tid + it * 256;
            int row = f >> 5, c16 = f & 31;
            uint32_t off = (uint32_t)(row * AKST + c16 * 8) * 2;
            CPA16(ks + off, kb + (size_t)row * 256 + c16 * 8);
            CPA16(vs + off, vb + (size_t)row * 256 + c16 * 8);
        }
    };

    ISSUEKV(0, 0); CPC();
    __syncthreads();

    uint32_t Qf[16][4];
    {
        const uint32_t qbase = smb + ((m0 + a_ro) * AKST + a_co) * 2;
#pragma unroll
        for (int kc = 0; kc < 16; ++kc) ldmx4(Qf[kc], qbase + kc * 32);
    }

    float O[32][4];
#pragma unroll
    for (int i = 0; i < 32; ++i)
#pragma unroll
        for (int c = 0; c < 4; ++c) O[i][c] = 0.f;
    float l0 = 0.f, l1 = 0.f;

    const float cexp = 0.0625f * 1.4426950408889634f;
    const int row0g = m0g + (lane >> 2);
    const int row1g = row0g + 8;

    for (int kt = 0; kt < ntiles; ++kt) {
        if (kt + 1 < ntiles) { ISSUEKV(kt + 1, (kt + 1) & 1); CPC(); CPW1(); }
        else                 { CPW0(); }
        __syncthreads();

        const int k0 = kt * 64;
        const uint32_t ks = smb + QB + (uint32_t)(kt & 1) * 2 * TB;
        const uint32_t vs = ks + TB;

#pragma unroll
        for (int j = 0; j < 4; ++j) {
            const int koff = k0 + 16 * j;
            if (koff > m0g + 15) break;

            float s0[4] = {0.f, 0.f, 0.f, 0.f};
            float s1[4] = {0.f, 0.f, 0.f, 0.f};
            const uint32_t bbase = ks + ((16 * j + b_ro) * AKST + b_co) * 2;
#pragma unroll
            for (int kc = 0; kc < 16; ++kc) {
                uint32_t Bf[4];
                ldmx4(Bf, bbase + kc * 32);
                mma_bf16(s0, Qf[kc], Bf);
                mma_bf16(s1, Qf[kc], Bf + 2);
            }

            float p0[4], p1[4];
#pragma unroll
            for (int c = 0; c < 4; ++c) {
                p0[c] = exp2f(s0[c] * cexp);
                p1[c] = exp2f(s1[c] * cexp);
            }
            if (koff + 15 > m0g) {
                const int c0g = koff + (lane & 3) * 2;
                if (c0g > row0g)     p0[0] = 0.f;
                if (c0g + 1 > row0g) p0[1] = 0.f;
                if (c0g > row1g)     p0[2] = 0.f;
                if (c0g + 1 > row1g) p0[3] = 0.f;
                if (c0g + 8 > row0g) p1[0] = 0.f;
                if (c0g + 9 > row0g) p1[1] = 0.f;
                if (c0g + 8 > row1g) p1[2] = 0.f;
                if (c0g + 9 > row1g) p1[3] = 0.f;
            }
            l0 += p0[0] + p0[1] + p1[0] + p1[1];
            l1 += p0[2] + p0[3] + p1[2] + p1[3];

            uint32_t P[4];
            P[0] = pack_bf16x2(p0[0], p0[1]);
            P[1] = pack_bf16x2(p0[2], p0[3]);
            P[2] = pack_bf16x2(p1[0], p1[1]);
            P[3] = pack_bf16x2(p1[2], p1[3]);

            const uint32_t vbase = vs + ((16 * j + a_ro) * AKST + a_co) * 2;
#pragma unroll
            for (int dt = 0; dt < 16; ++dt) {
                uint32_t Vf[4];
                ldmx4t(Vf, vbase + dt * 32);
                mma_bf16(O[2 * dt],     P, Vf);
                mma_bf16(O[2 * dt + 1], P, Vf + 2);
            }
        }
        __syncthreads();
    }

    l0 += __shfl_xor_sync(0xffffffffu, l0, 1);
    l0 += __shfl_xor_sync(0xffffffffu, l0, 2);
    l1 += __shfl_xor_sync(0xffffffffu, l1, 1);
    l1 += __shfl_xor_sync(0xffffffffu, l1, 2);
    const float inv0 = 1.0f / l0, inv1 = 1.0f / l1;

    __nv_bfloat16* o0 = og + (size_t)(b * TPATCH + row0g) * 256;
    __nv_bfloat16* o1 = og + (size_t)(b * TPATCH + row1g) * 256;
#pragma unroll
    for (int i = 0; i < 32; ++i) {
        const int d0 = i * 8 + (lane & 3) * 2;
        *(uint32_t*)(o0 + d0) = pack_bf16x2(O[i][0] * inv0, O[i][1] * inv0);
        *(uint32_t*)(o1 + d0) = pack_bf16x2(O[i][2] * inv1, O[i][3] * inv1);
    }
}

// ---------------------------------------------------------------------------
// Kernel 6: fused out-projection + head GEMM + MSE partials.
// Block = 64 rows.  Phase 1: out = abf @ WoT^T + b_out (BK=64, 2-stage
// cp.async; 8 warps 2(m)x4(n)), epilogue -> bf16 tile in smem (reuses
// stage 0).  Phase 2: pred = out @ WhT^T + b_head via mma, then
// (pred - tgt)^2 partial sum per block.
// ---------------------------------------------------------------------------
#define OH_ABYTES (64 * GST * 2)
#define OH_STAGE_B ((64 * GST + 256 * GST) * 2)
#define OH_DSMEM (2 * OH_STAGE_B + 32 * AKST * 2)

__global__ void __launch_bounds__(256) outhead_kernel(
    const __nv_bfloat16* __restrict__ A,      // attn out [32768,256]
    const __nv_bfloat16* __restrict__ Wt,     // W_out^T  [256,256]
    const float* __restrict__ bias,           // b_out
    const __nv_bfloat16* __restrict__ WhT,    // W_head^T [32,256]
    const float* __restrict__ bh,             // b_head
    const float* __restrict__ x,
    const float* __restrict__ stats,
    float* __restrict__ partials)
{
    extern __shared__ __nv_bfloat16 sm[];
    const uint32_t smb = smem_u32(sm);
    const uint32_t wh_s = smb + 2 * OH_STAGE_B;
    __shared__ float wsum[8];

    const int tid = threadIdx.x, wid = tid >> 5, lane = tid & 31;
    const int m0 = blockIdx.x * 64;           // within one batch (64 | 1024)
    const int wm = wid & 1, wn = wid >> 1;    // 2(m) x 4(n)

    const int lr = lane & 7, lg = lane >> 3;
    const int a_ro = lr + (lg & 1) * 8, a_co = (lg >> 1) * 8;
    const int b_ro = lr + (lg >> 1) * 8, b_co = (lg & 1) * 8;

    // load W_head^T (32 x 256) into smem above the stages.
    // FIX vs R16: cover ALL 1024 16B-chunks (32 rows x 32 chunks), not 512.
#pragma unroll
    for (int it = 0; it < 4; ++it) {
        int f = tid + it * 256;               // 0..1023
        int row = f >> 5, c16 = f & 31;
        *(uint4*)(sm + OH_STAGE_B + row * AKST + c16 * 8) =
            *(const uint4*)(WhT + (size_t)row * 256 + c16 * 8);
    }

    const __nv_bfloat16* Ab = A + (size_t)m0 * 256;

    auto ISSUE = [&](int c, int s) {
        const uint32_t sa = smb + (uint32_t)s * OH_STAGE_B;
        const uint32_t sb = sa + OH_ABYTES;
#pragma unroll
        for (int it = 0; it < 2; ++it) {      // A: 64x64 = 512 x16B
            int f = tid + it * 256;
            int row = f >> 3, c16 = f & 7;
            uint32_t off = (uint32_t)(row * GST + c16 * 8) * 2;
            CPA16(sa + off, Ab + (size_t)row * 256 + c * 64 + c16 * 8);
        }
#pragma unroll
        for (int it = 0; it < 8; ++it) {      // B: 256x64 = 2048 x16B
            int f = tid + it * 256;
            int row = f >> 3, c16 = f & 7;
            uint32_t off = (uint32_t)(row * GST + c16 * 8) * 2;
            CPA16(sb + off, Wt + (size_t)row * 256 + c * 64 + c16 * 8);
        }
    };

    float O[2][8][4];
#pragma unroll
    for (int mi = 0; mi < 2; ++mi)
#pragma unroll
        for (int ni = 0; ni < 8; ++ni)
#pragma unroll
            for (int c = 0; c < 4; ++c) O[mi][ni][c] = 0.f;

    auto COMP = [&](int s) {
        const uint32_t sa = smb + (uint32_t)s * OH_STAGE_B;
        const uint32_t abase = sa + ((wm * 32 + a_ro) * GST + a_co) * 2;
        const uint32_t bbase = sa + OH_ABYTES + ((wn * 64 + b_ro) * GST + b_co) * 2;
#pragma unroll
        for (int kc = 0; kc < 4; ++kc) {
            uint32_t Af[2][4];
            ldmx4(Af[0], abase + kc * 32);
            ldmx4(Af[1], abase + 16 * GST * 2 + kc * 32);
#pragma unroll
            for (int t = 0; t < 4; ++t) {
                uint32_t Bf[4];
                ldmx4(Bf, bbase + t * 16 * GST * 2 + kc * 32);
                mma_bf16(O[0][2 * t],     Af[0], Bf);
                mma_bf16(O[0][2 * t + 1], Af[0], Bf + 2);
                mma_bf16(O[1][2 * t],     Af[1], Bf);
                mma_bf16(O[1][2 * t + 1], Af[1], Bf + 2);
            }
        }
    };

    ISSUE(0, 0); CPC();
#pragma unroll
    for (int c = 0; c < 4; ++c) {
        if (c + 1 < 4) { ISSUE(c + 1, (c + 1) & 1); CPC(); CPW1(); }
        else           { CPW0(); }
        __syncthreads();
        COMP(c & 1);
        __syncthreads();
    }

    // epilogue: bias + bf16, into obuf (reuses stage 0: 64 x AKST <= stage)
#pragma unroll
    for (int mi = 0; mi < 2; ++mi) {
        const int r = wm * 32 + mi * 16 + (lane >> 2);
#pragma unroll
        for (int ni = 0; ni < 8; ++ni) {
            const int cg = wn * 64 + ni * 8 + (lane & 3) * 2;
            const float b0 = bias[cg], b1 = bias[cg + 1];
            *(uint32_t*)(sm + r * AKST + cg) =
                pack_bf16x2(O[mi][ni][0] + b0, O[mi][ni][1] + b1);
            *(uint32_t*)(sm + (r + 8) * AKST + cg) =
                pack_bf16x2(O[mi][ni][2] + b0, O[mi][ni][3] + b1);
        }
    }
    __syncthreads();

    // head phase: pred = obuf(64x256) @ WhT(32x256)^T
    const int wmh = wid & 3, wnh = wid >> 2;  // 4(m) x 2(n): 16 rows x 16 cols
    float S[2][4];
#pragma unroll
    for (int ni = 0; ni < 2; ++ni)
#pragma unroll
        for (int c = 0; c < 4; ++c) S[ni][c] = 0.f;

    const uint32_t ah = smb + ((wmh * 16 + a_ro) * AKST + a_co) * 2;
    const uint32_t bhh = wh_s + ((wnh * 16 + b_ro) * AKST + b_co) * 2;
#pragma unroll
    for (int kc = 0; kc < 16; ++kc) {
        uint32_t Af[4], Bf[4];
        ldmx4(Af, ah + kc * 32);
        ldmx4(Bf, bhh + kc * 32);
        mma_bf16(S[0], Af, Bf);
        mma_bf16(S[1], Af, Bf + 2);
    }

    // loss: (pred - normalized next patch)^2
    const int bidx = m0 >> 10;
    float mean, inv;
    batch_norm_params(stats, bidx, mean, inv);

    const int rg0 = m0 + wmh * 16 + (lane >> 2);
    const int rg1 = rg0 + 8;
    const int t0 = rg0 & 1023, t1 = rg1 & 1023;
    float sq = 0.f;
#pragma unroll
    for (int ni = 0; ni < 2; ++ni) {
        const int cg = wnh * 16 + ni * 8 + (lane & 3) * 2;
        const float bh0 = bh[cg], bh1 = bh[cg + 1];
        if (t0 < TPATCH - 1) {
            const float* tb = x + (size_t)bidx * LSEQ + (t0 + 1) * 32 + cg;
            float d0 = (S[ni][0] + bh0) - (tb[0] - mean) * inv;
            float d1 = (S[ni][1] + bh1) - (tb[1] - mean) * inv;
            sq += d0 * d0 + d1 * d1;
        }
        if (t1 < TPATCH - 1) {
            const float* tb = x + (size_t)bidx * LSEQ + (t1 + 1) * 32 + cg;
            float d2 = (S[ni][2] + bh0) - (tb[0] - mean) * inv;
            float d3 = (S[ni][3] + bh1) - (tb[1] - mean) * inv;
            sq += d2 * d2 + d3 * d3;
        }
    }
#pragma unroll
    for (int off = 16; off > 0; off >>= 1)
        sq += __shfl_xor_sync(0xffffffffu, sq, off);
    if (lane == 0) wsum[wid] = sq;
    __syncthreads();
    if (tid == 0) {
        float s = 0.f;
#pragma unroll
        for (int u = 0; u < 8; ++u) s += wsum[u];
        partials[blockIdx.x] = s;
    }
}

// ---------------------------------------------------------------------------
// Kernel 7: final deterministic reduction -> loss scalar (512 partials)
// ---------------------------------------------------------------------------
__global__ void __launch_bounds__(512) final_reduce_kernel(
    const float* __restrict__ partials, float* __restrict__ out)
{
    __shared__ float sm2[512];
    const int tid = threadIdx.x;
    sm2[tid] = partials[tid];
    __syncthreads();
    for (int st = 256; st > 0; st >>= 1) {
        if (tid < st) sm2[tid] += sm2[tid + st];
        __syncthreads();
    }
    if (tid == 0)
        out[0] = sm2[0] / (float)(BATCH * (TPATCH - 1) * PS);
}

// ---------------------------------------------------------------------------
// Launch
// ---------------------------------------------------------------------------
extern "C" void kernel_launch(void* const* d_in, const int* in_sizes, int n_in,
                              void* d_out, int out_size)
{
    const float* x      = (const float*)d_in[0];
    const float* W_proj = (const float*)d_in[1];
    const float* b_proj = (const float*)d_in[2];
    const float* W_qkv  = (const float*)d_in[3];
    const float* b_qkv  = (const float*)d_in[4];
    const float* W_out  = (const float*)d_in[5];
    const float* b_out  = (const float*)d_in[6];
    const float* W_head = (const float*)d_in[7];
    const float* b_head = (const float*)d_in[8];
    float* out = (float*)d_out;

    float *nst, *parts;
    __nv_bfloat16 *hbf, *qbf, *kbf, *vbf, *abf, *wqT, *woT, *whT;
    cudaGetSymbolAddress((void**)&nst,  g_nstats);
    cudaGetSymbolAddress((void**)&hbf,  g_hbf);
    cudaGetSymbolAddress((void**)&qbf,  g_qbf);
    cudaGetSymbolAddress((void**)&kbf,  g_kbf);
    cudaGetSymbolAddress((void**)&vbf,  g_vbf);
    cudaGetSymbolAddress((void**)&abf,  g_abf);
    cudaGetSymbolAddress((void**)&wqT,  g_wqkvT);
    cudaGetSymbolAddress((void**)&woT,  g_woutT);
    cudaGetSymbolAddress((void**)&whT,  g_wheadT);
    cudaGetSymbolAddress((void**)&parts, g_partials);

    cudaFuncSetAttribute(gemm_mma_kernel,
                         cudaFuncAttributeMaxDynamicSharedMemorySize, GEMM_DSMEM);
    cudaFuncSetAttribute(attn_mma_kernel,
                         cudaFuncAttributeMaxDynamicSharedMemorySize, ATTN_DSMEM);
    cudaFuncSetAttribute(outhead_kernel,
                         cudaFuncAttributeMaxDynamicSharedMemorySize, OH_DSMEM);

    // 1. instance norm stats (normalization fused into consumers)
    norm_stat_kernel<<<256, 256>>>(x, nst);
    // 2. weight transpose -> bf16
    conv_w_kernel<<<768, 256>>>(W_qkv, W_out, W_head, wqT, woT, whT);
    // 3. patch embedding (norm fused, 4-row ILP)
    embed_kernel<<<ROWS_TOTAL / 64, 256>>>(x, nst, W_proj, b_proj, hbf);
    // 4. QKV GEMM (pipelined mma.sync)
    gemm_mma_kernel<<<dim3(ROWS_TOTAL / 128, 6), 256, GEMM_DSMEM>>>(
        hbf, wqT, b_qkv, qbf, kbf, vbf);
    // 5. causal flash attention
    attn_mma_kernel<<<dim3(TPATCH / 128, BATCH), 256, ATTN_DSMEM>>>(
        qbf, kbf, vbf, abf);
    // 6. fused out-projection + head + loss partials
    outhead_kernel<<<ROWS_TOTAL / 64, 256, OH_DSMEM>>>(
        abf, woT, b_out, whT, b_head, x, nst, parts);
    // 7. final scalar
    final_reduce_kernel<<<1, 512>>>(parts, out);
}